// round 3
// baseline (speedup 1.0000x reference)
#include <cuda_runtime.h>
#include <cuda_bf16.h>

#define N_NODES 50000
#define N_EDGES 800000
#define HEADS 8
#define ADIM 8
#define HD 64            // HEADS*ADIM
#define CLAMP_V 5.0f
#define SCAN_BLK 196     // ceil(50000/256)

// ---------------- scratch (device globals: allocation-free rule) ----------------
__device__ __align__(16) float g_Q[N_NODES * HD];
__device__ __align__(16) float g_K[N_NODES * HD];
__device__ __align__(16) float g_V[N_NODES * HD];
__device__ __align__(16) float g_w[N_EDGES * HEADS];   // exp(clamped score)
__device__ int g_count[N_NODES];
__device__ int g_off[N_NODES + 1];
__device__ int g_cursor[N_NODES];
__device__ int g_order[N_EDGES];
__device__ int g_bsum[SCAN_BLK];
__device__ int g_boff[SCAN_BLK];

// ---------------- f32x2 packed FMA helpers (FFMA2) ----------------
__device__ __forceinline__ unsigned long long pk2(float lo, float hi) {
    unsigned long long r;
    asm("mov.b64 %0, {%1, %2};" : "=l"(r) : "f"(lo), "f"(hi));
    return r;
}
__device__ __forceinline__ void fma2(unsigned long long& d, unsigned long long a, unsigned long long b) {
    asm("fma.rn.f32x2 %0, %1, %2, %0;" : "+l"(d) : "l"(a), "l"(b));
}
__device__ __forceinline__ float2 upk2(unsigned long long v) {
    float lo, hi;
    asm("mov.b64 {%0, %1}, %2;" : "=f"(lo), "=f"(hi) : "l"(v));
    return make_float2(lo, hi);
}

// ---------------- kernel 1: QKV = x @ qkv_weight.T + bias ----------------
__global__ __launch_bounds__(256) void qkv_kernel(
    const float* __restrict__ x, const float* __restrict__ W, const float* __restrict__ bias)
{
    __shared__ float xS[64 * 68];
    __shared__ float wS[64 * 68];   // wS[k*68 + c] = W[(part*64+c)*64 + k]
    const int part = blockIdx.y;
    const int row0 = blockIdx.x * 64;
    const int tid = threadIdx.x;

    #pragma unroll
    for (int p = 0; p < 4; p++) {
        int idx = tid + p * 256;         // float4 index into 64x64 tile
        int r = idx >> 4, c4 = idx & 15;
        float4 v = make_float4(0.f, 0.f, 0.f, 0.f);
        int gr = row0 + r;
        if (gr < N_NODES) v = ((const float4*)x)[gr * 16 + c4];
        *(float4*)&xS[r * 68 + c4 * 4] = v;
    }
    #pragma unroll
    for (int p = 0; p < 4; p++) {
        int idx = tid + p * 256;
        int c = idx >> 4, f = idx & 15;
        float4 v = ((const float4*)W)[(part * 64 + c) * 16 + f];
        wS[(f * 4 + 0) * 68 + c] = v.x;
        wS[(f * 4 + 1) * 68 + c] = v.y;
        wS[(f * 4 + 2) * 68 + c] = v.z;
        wS[(f * 4 + 3) * 68 + c] = v.w;
    }
    __syncthreads();

    const int tx = tid & 15, ty = tid >> 4;   // 4 cols x 4 rows per thread
    unsigned long long acc[4][2];
    #pragma unroll
    for (int i = 0; i < 4; i++) { acc[i][0] = 0ull; acc[i][1] = 0ull; }

    #pragma unroll 4
    for (int k = 0; k < 64; k++) {
        float4 b = *(float4*)&wS[k * 68 + tx * 4];
        unsigned long long b0 = pk2(b.x, b.y), b1 = pk2(b.z, b.w);
        #pragma unroll
        for (int i = 0; i < 4; i++) {
            float a = xS[(ty * 4 + i) * 68 + k];
            unsigned long long a2 = pk2(a, a);
            fma2(acc[i][0], a2, b0);
            fma2(acc[i][1], a2, b1);
        }
    }

    float* outBase = (part == 0) ? g_Q : (part == 1 ? g_K : g_V);
    float4 bv = ((const float4*)bias)[part * 16 + tx];
    #pragma unroll
    for (int i = 0; i < 4; i++) {
        int gr = row0 + ty * 4 + i;
        if (gr < N_NODES) {
            float2 p0 = upk2(acc[i][0]), p1 = upk2(acc[i][1]);
            float4 o = make_float4(p0.x + bv.x, p0.y + bv.y, p1.x + bv.z, p1.y + bv.w);
            *(float4*)&outBase[gr * 64 + tx * 4] = o;
        }
    }
}

// ---------------- CSR construction ----------------
__global__ void zero_kernel() {
    int i = blockIdx.x * blockDim.x + threadIdx.x;
    if (i < N_NODES) g_count[i] = 0;
}
__global__ void count_kernel(const int* __restrict__ eidx) {
    int e = blockIdx.x * blockDim.x + threadIdx.x;
    if (e < N_EDGES) atomicAdd(&g_count[eidx[e]], 1);
}

// phase A: per-block sums of g_count (196 blocks x 256 threads)
__global__ __launch_bounds__(256) void scanA_kernel() {
    __shared__ int ws[8];
    int t = threadIdx.x, i = blockIdx.x * 256 + t;
    int v = (i < N_NODES) ? g_count[i] : 0;
    #pragma unroll
    for (int o = 16; o > 0; o >>= 1) v += __shfl_down_sync(0xffffffffu, v, o);
    if ((t & 31) == 0) ws[t >> 5] = v;
    __syncthreads();
    if (t == 0) {
        int s = 0;
        #pragma unroll
        for (int w = 0; w < 8; w++) s += ws[w];
        g_bsum[blockIdx.x] = s;
    }
}
// phase B: exclusive scan over 196 partials (1 block)
__global__ __launch_bounds__(256) void scanB_kernel() {
    __shared__ int ws[8];
    int t = threadIdx.x, lane = t & 31, w = t >> 5;
    int v = (t < SCAN_BLK) ? g_bsum[t] : 0;
    int x = v;
    #pragma unroll
    for (int o = 1; o < 32; o <<= 1) {
        int y = __shfl_up_sync(0xffffffffu, x, o);
        if (lane >= o) x += y;
    }
    if (lane == 31) ws[w] = x;
    __syncthreads();
    if (t == 0) {
        int run = 0;
        #pragma unroll
        for (int k = 0; k < 8; k++) { int tmp = ws[k]; ws[k] = run; run += tmp; }
    }
    __syncthreads();
    if (t < SCAN_BLK) g_boff[t] = x - v + ws[w];
    if (t == 0) g_off[N_NODES] = N_EDGES;
}
// phase C: local exclusive scan + block offset -> g_off / g_cursor
__global__ __launch_bounds__(256) void scanC_kernel() {
    __shared__ int ws[8];
    int t = threadIdx.x, lane = t & 31, w = t >> 5;
    int i = blockIdx.x * 256 + t;
    int v = (i < N_NODES) ? g_count[i] : 0;
    int x = v;
    #pragma unroll
    for (int o = 1; o < 32; o <<= 1) {
        int y = __shfl_up_sync(0xffffffffu, x, o);
        if (lane >= o) x += y;
    }
    if (lane == 31) ws[w] = x;
    __syncthreads();
    if (t == 0) {
        int run = 0;
        #pragma unroll
        for (int k = 0; k < 8; k++) { int tmp = ws[k]; ws[k] = run; run += tmp; }
    }
    __syncthreads();
    if (i < N_NODES) {
        int excl = x - v + ws[w] + g_boff[blockIdx.x];
        g_off[i] = excl;
        g_cursor[i] = excl;
    }
}
__global__ void scatter_kernel(const int* __restrict__ eidx) {
    int e = blockIdx.x * blockDim.x + threadIdx.x;
    if (e < N_EDGES) {
        int dst = eidx[e];
        int pos = atomicAdd(&g_cursor[dst], 1);
        g_order[pos] = e;
    }
}

// ---------------- kernel 2: fused edge GEMM + conn + score ----------------
// block = 128 edges, 256 threads. thread = 4 edges x 1 head x {Ew(8), Eb(8)}.
// NOTE: no min-blocks clause — avoid the 128-reg cap (spill suspect). smem
// (70KB) still allows 2 blocks/SM; reg budget 512thr x ~110 regs fits 64K.
__global__ __launch_bounds__(256) void edge_kernel(
    const float* __restrict__ cf, const float* __restrict__ EW,
    const float* __restrict__ Ebias, const int* __restrict__ eidx,
    const float* __restrict__ Aw, float* __restrict__ conn_out)
{
    extern __shared__ float sm[];
    float* cfS = sm;                      // 128*68
    float* wS = cfS + 128 * 68;           // 64*132 : wS[k*132 + n] = EW[n*64+k]
    float* awS = wS + 64 * 132;           // 64
    float* ebS = awS + 64;                // 128
    int* sDst = (int*)(ebS + 128);        // 128
    int* sSrc = sDst + 128;               // 128

    const int tid = threadIdx.x;
    const int e0 = blockIdx.x * 128;

    #pragma unroll
    for (int p = 0; p < 8; p++) {
        int idx = tid + p * 256;          // float4 index over 128x64 cf tile
        int r = idx >> 4, c4 = idx & 15;
        float4 v = ((const float4*)cf)[(e0 + r) * 16 + c4];
        *(float4*)&cfS[r * 68 + c4 * 4] = v;
    }
    #pragma unroll
    for (int p = 0; p < 8; p++) {
        int idx = tid + p * 256;          // float4 index over 128x64 EW
        int n = idx >> 4, f = idx & 15;
        float4 v = ((const float4*)EW)[n * 16 + f];
        wS[(f * 4 + 0) * 132 + n] = v.x;
        wS[(f * 4 + 1) * 132 + n] = v.y;
        wS[(f * 4 + 2) * 132 + n] = v.z;
        wS[(f * 4 + 3) * 132 + n] = v.w;
    }
    if (tid < 64) awS[tid] = Aw[tid];
    if (tid >= 64 && tid < 192) ebS[tid - 64] = Ebias[tid - 64];
    if (tid < 128) {
        sDst[tid] = eidx[e0 + tid];
        sSrc[tid] = eidx[N_EDGES + e0 + tid];
    }
    __syncthreads();

    const int tx = tid & 7;               // head
    const int tg = tid >> 3;              // edge group (4 edges)

    unsigned long long acc[4][8];
    #pragma unroll
    for (int i = 0; i < 4; i++)
        #pragma unroll
        for (int p = 0; p < 8; p++) acc[i][p] = 0ull;

    #pragma unroll 2
    for (int k = 0; k < 64; k++) {
        const float* wr = &wS[k * 132];
        float4 w0 = *(const float4*)&wr[tx * 8];
        float4 w1 = *(const float4*)&wr[tx * 8 + 4];
        float4 w2 = *(const float4*)&wr[64 + tx * 8];
        float4 w3 = *(const float4*)&wr[64 + tx * 8 + 4];
        unsigned long long b[8];
        b[0] = pk2(w0.x, w0.y); b[1] = pk2(w0.z, w0.w);
        b[2] = pk2(w1.x, w1.y); b[3] = pk2(w1.z, w1.w);
        b[4] = pk2(w2.x, w2.y); b[5] = pk2(w2.z, w2.w);
        b[6] = pk2(w3.x, w3.y); b[7] = pk2(w3.z, w3.w);
        #pragma unroll
        for (int i = 0; i < 4; i++) {
            float a = cfS[(tg * 4 + i) * 68 + k];
            unsigned long long a2 = pk2(a, a);
            #pragma unroll
            for (int p = 0; p < 8; p++) fma2(acc[i][p], a2, b[p]);
        }
    }

    // epilogue per edge: conn1 -> signed sqrt -> +Eb -> relu -> write; score -> w
    #pragma unroll
    for (int i = 0; i < 4; i++) {
        int el = tg * 4 + i;
        int e = e0 + el;
        int d = sDst[el], s = sSrc[el];
        float4 q0 = ((const float4*)g_Q)[d * 16 + tx * 2];
        float4 q1 = ((const float4*)g_Q)[d * 16 + tx * 2 + 1];
        float4 k0 = ((const float4*)g_K)[s * 16 + tx * 2];
        float4 k1 = ((const float4*)g_K)[s * 16 + tx * 2 + 1];
        float qk[8] = {q0.x + k0.x, q0.y + k0.y, q0.z + k0.z, q0.w + k0.w,
                       q1.x + k1.x, q1.y + k1.y, q1.z + k1.z, q1.w + k1.w};
        float ew[8], eb[8];
        #pragma unroll
        for (int p = 0; p < 4; p++) {
            float2 u = upk2(acc[i][p]);
            ew[2 * p] = u.x; ew[2 * p + 1] = u.y;
            float2 v = upk2(acc[i][4 + p]);
            eb[2 * p] = v.x; eb[2 * p + 1] = v.y;
        }
        float conn[8];
        #pragma unroll
        for (int j = 0; j < 8; j++) {
            float c1 = qk[j] * (ew[j] + ebS[tx * 8 + j]);
            float c2 = copysignf(sqrtf(fabsf(c1)), c1);
            conn[j] = fmaxf(c2 + (eb[j] + ebS[64 + tx * 8 + j]), 0.f);
        }
        float* co = &conn_out[(long long)e * 64 + tx * 8];
        *(float4*)co = make_float4(conn[0], conn[1], conn[2], conn[3]);
        *(float4*)(co + 4) = make_float4(conn[4], conn[5], conn[6], conn[7]);
        float sc = 0.f;
        #pragma unroll
        for (int j = 0; j < 8; j++) sc = fmaf(conn[j], awS[j * 8 + tx], sc);
        sc = fminf(fmaxf(sc, -CLAMP_V), CLAMP_V);
        g_w[e * 8 + tx] = expf(sc);
    }
}

// ---------------- kernel 3: per-node aggregation (warp per node) ----------------
__global__ __launch_bounds__(256) void node_kernel(
    const float* __restrict__ conn_out, const int* __restrict__ eidx,
    const float* __restrict__ Bw, float* __restrict__ No)
{
    __shared__ float bwS[512];
    int tid = threadIdx.x;
    bwS[tid] = Bw[tid];
    bwS[tid + 256] = Bw[tid + 256];
    __syncthreads();

    const int warp = tid >> 5, lane = tid & 31;
    const int n = blockIdx.x * 8 + warp;
    const int j0 = g_off[n], j1 = g_off[n + 1];
    const int h0 = lane >> 3, h1 = h0 + 4, c = lane & 7, base = lane & 24;
    const int* srcArr = eidx + N_EDGES;

    float s0 = 0.f, s1 = 0.f, agg0 = 0.f, agg1 = 0.f, rv0 = 0.f, rv1 = 0.f;
    int e = (j0 < j1) ? g_order[j0] : 0;
    for (int j = j0; j < j1; j++) {
        int e_next = (j + 1 < j1) ? g_order[j + 1] : 0;  // prefetch: breaks dep chain
        int src = srcArr[e];
        float w0 = g_w[e * 8 + h0];
        float w1 = g_w[e * 8 + h1];
        float c0 = conn_out[(long long)e * 64 + lane];
        float c1 = conn_out[(long long)e * 64 + 32 + lane];
        float v0 = g_V[src * 64 + lane];
        float v1 = g_V[src * 64 + 32 + lane];
        s0 += w0; s1 += w1;
        agg0 = fmaf(w0, v0, agg0); rv0 = fmaf(w0, c0, rv0);
        agg1 = fmaf(w1, v1, agg1); rv1 = fmaf(w1, c1, rv1);
        e = e_next;
    }
    float inv0 = (s0 > 0.f) ? 1.f / s0 : 0.f;
    float inv1 = (s1 > 0.f) ? 1.f / s1 : 0.f;
    float rn0 = rv0 * inv0, rn1 = rv1 * inv1;
    float o0 = 0.f, o1 = 0.f;
    #pragma unroll
    for (int d = 0; d < 8; d++) {
        float r0 = __shfl_sync(0xffffffffu, rn0, base + d);
        float r1 = __shfl_sync(0xffffffffu, rn1, base + d);
        o0 = fmaf(r0, bwS[d * 64 + h0 * 8 + c], o0);
        o1 = fmaf(r1, bwS[d * 64 + h1 * 8 + c], o1);
    }
    No[n * 64 + lane] = fmaf(agg0, inv0, o0);
    No[n * 64 + 32 + lane] = fmaf(agg1, inv1, o1);
}

// ---------------- launch ----------------
extern "C" void kernel_launch(void* const* d_in, const int* in_sizes, int n_in,
                              void* d_out, int out_size)
{
    const float* x       = (const float*)d_in[0];
    const float* cf      = (const float*)d_in[1];
    const int*   eidx    = (const int*)d_in[2];
    const float* qkvW    = (const float*)d_in[3];
    const float* qkvB    = (const float*)d_in[4];
    const float* EW      = (const float*)d_in[5];
    const float* EB      = (const float*)d_in[6];
    const float* Aw      = (const float*)d_in[7];
    const float* Bw      = (const float*)d_in[8];

    float* No = (float*)d_out;
    float* conn_out = No + (size_t)N_NODES * 64;

    const int edge_smem = (128 * 68 + 64 * 132 + 64 + 128) * 4 + 256 * 4;
    cudaFuncSetAttribute(edge_kernel, cudaFuncAttributeMaxDynamicSharedMemorySize, edge_smem);

    // ncu (-s 5 -c 1) profiles OUR 4th launch (harness pre-issues ~2).
    // Put edge_kernel there. Dependencies: edge needs only qkv;
    // node needs edge + scatter; scanC -> scatter.
    zero_kernel<<<(N_NODES + 255) / 256, 256>>>();                         // 1
    qkv_kernel<<<dim3((N_NODES + 63) / 64, 3), 256>>>(x, qkvW, qkvB);      // 2
    count_kernel<<<(N_EDGES + 255) / 256, 256>>>(eidx);                    // 3
    edge_kernel<<<N_EDGES / 128, 256, edge_smem>>>(cf, EW, EB, eidx, Aw, conn_out); // 4 <- profiled
    scanA_kernel<<<SCAN_BLK, 256>>>();                                     // 5
    scanB_kernel<<<1, 256>>>();                                            // 6
    scanC_kernel<<<SCAN_BLK, 256>>>();                                     // 7
    scatter_kernel<<<(N_EDGES + 255) / 256, 256>>>(eidx);                  // 8
    node_kernel<<<N_NODES / 8, 256>>>(conn_out, eidx, Bw, No);             // 9
}

// round 4
// speedup vs baseline: 1.0419x; 1.0419x over previous
#include <cuda_runtime.h>
#include <cuda_bf16.h>

#define N_NODES 50000
#define N_EDGES 800000
#define HEADS 8
#define ADIM 8
#define HD 64            // HEADS*ADIM
#define CLAMP_V 5.0f
#define SCAN_BLK 196     // ceil(50000/256)

// ---------------- scratch (device globals: allocation-free rule) ----------------
__device__ __align__(16) float g_Q[N_NODES * HD];
__device__ __align__(16) float g_K[N_NODES * HD];
__device__ __align__(16) float g_V[N_NODES * HD];
__device__ __align__(16) float g_w[N_EDGES * HEADS];   // exp(clamped score)
__device__ int g_count[N_NODES];
__device__ int g_off[N_NODES + 1];
__device__ int g_cursor[N_NODES];
__device__ int g_order[N_EDGES];
__device__ int g_bsum[SCAN_BLK];
__device__ int g_boff[SCAN_BLK];

// ---------------- f32x2 packed FMA helpers (FFMA2) ----------------
__device__ __forceinline__ unsigned long long pk2(float lo, float hi) {
    unsigned long long r;
    asm("mov.b64 %0, {%1, %2};" : "=l"(r) : "f"(lo), "f"(hi));
    return r;
}
__device__ __forceinline__ void fma2(unsigned long long& d, unsigned long long a, unsigned long long b) {
    asm("fma.rn.f32x2 %0, %1, %2, %0;" : "+l"(d) : "l"(a), "l"(b));
}
__device__ __forceinline__ float2 upk2(unsigned long long v) {
    float lo, hi;
    asm("mov.b64 {%0, %1}, %2;" : "=f"(lo), "=f"(hi) : "l"(v));
    return make_float2(lo, hi);
}

// ---------------- kernel 1: QKV = x @ qkv_weight.T + bias ----------------
__global__ __launch_bounds__(256) void qkv_kernel(
    const float* __restrict__ x, const float* __restrict__ W, const float* __restrict__ bias)
{
    __shared__ float xS[64 * 68];
    __shared__ float wS[64 * 68];   // wS[k*68 + c] = W[(part*64+c)*64 + k]
    const int part = blockIdx.y;
    const int row0 = blockIdx.x * 64;
    const int tid = threadIdx.x;

    #pragma unroll
    for (int p = 0; p < 4; p++) {
        int idx = tid + p * 256;         // float4 index into 64x64 tile
        int r = idx >> 4, c4 = idx & 15;
        float4 v = make_float4(0.f, 0.f, 0.f, 0.f);
        int gr = row0 + r;
        if (gr < N_NODES) v = ((const float4*)x)[gr * 16 + c4];
        *(float4*)&xS[r * 68 + c4 * 4] = v;
    }
    #pragma unroll
    for (int p = 0; p < 4; p++) {
        int idx = tid + p * 256;
        int c = idx >> 4, f = idx & 15;
        float4 v = ((const float4*)W)[(part * 64 + c) * 16 + f];
        wS[(f * 4 + 0) * 68 + c] = v.x;
        wS[(f * 4 + 1) * 68 + c] = v.y;
        wS[(f * 4 + 2) * 68 + c] = v.z;
        wS[(f * 4 + 3) * 68 + c] = v.w;
    }
    __syncthreads();

    const int tx = tid & 15, ty = tid >> 4;   // 4 cols x 4 rows per thread
    unsigned long long acc[4][2];
    #pragma unroll
    for (int i = 0; i < 4; i++) { acc[i][0] = 0ull; acc[i][1] = 0ull; }

    #pragma unroll 4
    for (int k = 0; k < 64; k++) {
        float4 b = *(float4*)&wS[k * 68 + tx * 4];
        unsigned long long b0 = pk2(b.x, b.y), b1 = pk2(b.z, b.w);
        #pragma unroll
        for (int i = 0; i < 4; i++) {
            float a = xS[(ty * 4 + i) * 68 + k];
            unsigned long long a2 = pk2(a, a);
            fma2(acc[i][0], a2, b0);
            fma2(acc[i][1], a2, b1);
        }
    }

    float* outBase = (part == 0) ? g_Q : (part == 1 ? g_K : g_V);
    float4 bv = ((const float4*)bias)[part * 16 + tx];
    #pragma unroll
    for (int i = 0; i < 4; i++) {
        int gr = row0 + ty * 4 + i;
        if (gr < N_NODES) {
            float2 p0 = upk2(acc[i][0]), p1 = upk2(acc[i][1]);
            float4 o = make_float4(p0.x + bv.x, p0.y + bv.y, p1.x + bv.z, p1.y + bv.w);
            *(float4*)&outBase[gr * 64 + tx * 4] = o;
        }
    }
}

// ---------------- CSR construction ----------------
__global__ void zero_kernel() {
    int i = blockIdx.x * blockDim.x + threadIdx.x;
    if (i < N_NODES) g_count[i] = 0;
}
__global__ void count_kernel(const int* __restrict__ eidx) {
    int e = blockIdx.x * blockDim.x + threadIdx.x;
    if (e < N_EDGES) atomicAdd(&g_count[eidx[e]], 1);
}

// phase A: per-block sums of g_count (196 blocks x 256 threads)
__global__ __launch_bounds__(256) void scanA_kernel() {
    __shared__ int ws[8];
    int t = threadIdx.x, i = blockIdx.x * 256 + t;
    int v = (i < N_NODES) ? g_count[i] : 0;
    #pragma unroll
    for (int o = 16; o > 0; o >>= 1) v += __shfl_down_sync(0xffffffffu, v, o);
    if ((t & 31) == 0) ws[t >> 5] = v;
    __syncthreads();
    if (t == 0) {
        int s = 0;
        #pragma unroll
        for (int w = 0; w < 8; w++) s += ws[w];
        g_bsum[blockIdx.x] = s;
    }
}
// phase B: exclusive scan over 196 partials (1 block)
__global__ __launch_bounds__(256) void scanB_kernel() {
    __shared__ int ws[8];
    int t = threadIdx.x, lane = t & 31, w = t >> 5;
    int v = (t < SCAN_BLK) ? g_bsum[t] : 0;
    int x = v;
    #pragma unroll
    for (int o = 1; o < 32; o <<= 1) {
        int y = __shfl_up_sync(0xffffffffu, x, o);
        if (lane >= o) x += y;
    }
    if (lane == 31) ws[w] = x;
    __syncthreads();
    if (t == 0) {
        int run = 0;
        #pragma unroll
        for (int k = 0; k < 8; k++) { int tmp = ws[k]; ws[k] = run; run += tmp; }
    }
    __syncthreads();
    if (t < SCAN_BLK) g_boff[t] = x - v + ws[w];
    if (t == 0) g_off[N_NODES] = N_EDGES;
}
// phase C: local exclusive scan + block offset -> g_off / g_cursor
__global__ __launch_bounds__(256) void scanC_kernel() {
    __shared__ int ws[8];
    int t = threadIdx.x, lane = t & 31, w = t >> 5;
    int i = blockIdx.x * 256 + t;
    int v = (i < N_NODES) ? g_count[i] : 0;
    int x = v;
    #pragma unroll
    for (int o = 1; o < 32; o <<= 1) {
        int y = __shfl_up_sync(0xffffffffu, x, o);
        if (lane >= o) x += y;
    }
    if (lane == 31) ws[w] = x;
    __syncthreads();
    if (t == 0) {
        int run = 0;
        #pragma unroll
        for (int k = 0; k < 8; k++) { int tmp = ws[k]; ws[k] = run; run += tmp; }
    }
    __syncthreads();
    if (i < N_NODES) {
        int excl = x - v + ws[w] + g_boff[blockIdx.x];
        g_off[i] = excl;
        g_cursor[i] = excl;
    }
}
__global__ void scatter_kernel(const int* __restrict__ eidx) {
    int e = blockIdx.x * blockDim.x + threadIdx.x;
    if (e < N_EDGES) {
        int dst = eidx[e];
        int pos = atomicAdd(&g_cursor[dst], 1);
        g_order[pos] = e;
    }
}

// ---------------- kernel 2: fused edge GEMM + conn + score ----------------
// block = 128 edges, 256 threads. thread = 4 edges x 1 head x {Ew(8), Eb(8)}.
// Mainloop k-blocked by 4: per 4-k step, activation values come from 4
// LDS.128 (one float4 of k-values per edge) instead of 16 LDS.32 —
// cuts mainloop LDS from 8/k to 5/k (L1 was 94.8% = the bottleneck).
__global__ __launch_bounds__(256) void edge_kernel(
    const float* __restrict__ cf, const float* __restrict__ EW,
    const float* __restrict__ Ebias, const int* __restrict__ eidx,
    const float* __restrict__ Aw, float* __restrict__ conn_out)
{
    extern __shared__ float sm[];
    float* cfS = sm;                      // 128*68
    float* wS = cfS + 128 * 68;           // 64*132 : wS[k*132 + n] = EW[n*64+k]
    float* awS = wS + 64 * 132;           // 64
    float* ebS = awS + 64;                // 128
    int* sDst = (int*)(ebS + 128);        // 128
    int* sSrc = sDst + 128;               // 128

    const int tid = threadIdx.x;
    const int e0 = blockIdx.x * 128;

    #pragma unroll
    for (int p = 0; p < 8; p++) {
        int idx = tid + p * 256;          // float4 index over 128x64 cf tile
        int r = idx >> 4, c4 = idx & 15;
        float4 v = ((const float4*)cf)[(e0 + r) * 16 + c4];
        *(float4*)&cfS[r * 68 + c4 * 4] = v;
    }
    #pragma unroll
    for (int p = 0; p < 8; p++) {
        int idx = tid + p * 256;          // float4 index over 128x64 EW
        int n = idx >> 4, f = idx & 15;
        float4 v = ((const float4*)EW)[n * 16 + f];
        wS[(f * 4 + 0) * 132 + n] = v.x;
        wS[(f * 4 + 1) * 132 + n] = v.y;
        wS[(f * 4 + 2) * 132 + n] = v.z;
        wS[(f * 4 + 3) * 132 + n] = v.w;
    }
    if (tid < 64) awS[tid] = Aw[tid];
    if (tid >= 64 && tid < 192) ebS[tid - 64] = Ebias[tid - 64];
    if (tid < 128) {
        sDst[tid] = eidx[e0 + tid];
        sSrc[tid] = eidx[N_EDGES + e0 + tid];
    }
    __syncthreads();

    const int tx = tid & 7;               // head
    const int tg = tid >> 3;              // edge group (4 edges)

    unsigned long long acc[4][8];
    #pragma unroll
    for (int i = 0; i < 4; i++)
        #pragma unroll
        for (int p = 0; p < 8; p++) acc[i][p] = 0ull;

    #pragma unroll 1
    for (int k4 = 0; k4 < 64; k4 += 4) {
        // 4 edges x 4 k-values in one vector load each
        float4 a4[4];
        #pragma unroll
        for (int i = 0; i < 4; i++)
            a4[i] = *(const float4*)&cfS[(tg * 4 + i) * 68 + k4];

        #pragma unroll
        for (int kk = 0; kk < 4; kk++) {
            const float* wr = &wS[(k4 + kk) * 132];
            float4 w0 = *(const float4*)&wr[tx * 8];
            float4 w1 = *(const float4*)&wr[tx * 8 + 4];
            float4 w2 = *(const float4*)&wr[64 + tx * 8];
            float4 w3 = *(const float4*)&wr[64 + tx * 8 + 4];
            unsigned long long b[8];
            b[0] = pk2(w0.x, w0.y); b[1] = pk2(w0.z, w0.w);
            b[2] = pk2(w1.x, w1.y); b[3] = pk2(w1.z, w1.w);
            b[4] = pk2(w2.x, w2.y); b[5] = pk2(w2.z, w2.w);
            b[6] = pk2(w3.x, w3.y); b[7] = pk2(w3.z, w3.w);
            #pragma unroll
            for (int i = 0; i < 4; i++) {
                float a = (kk == 0) ? a4[i].x : (kk == 1) ? a4[i].y
                        : (kk == 2) ? a4[i].z : a4[i].w;
                unsigned long long a2 = pk2(a, a);
                #pragma unroll
                for (int p = 0; p < 8; p++) fma2(acc[i][p], a2, b[p]);
            }
        }
    }

    // epilogue per edge: conn1 -> signed sqrt -> +Eb -> relu -> write; score -> w
    #pragma unroll
    for (int i = 0; i < 4; i++) {
        int el = tg * 4 + i;
        int e = e0 + el;
        int d = sDst[el], s = sSrc[el];
        float4 q0 = ((const float4*)g_Q)[d * 16 + tx * 2];
        float4 q1 = ((const float4*)g_Q)[d * 16 + tx * 2 + 1];
        float4 k0 = ((const float4*)g_K)[s * 16 + tx * 2];
        float4 k1 = ((const float4*)g_K)[s * 16 + tx * 2 + 1];
        float qk[8] = {q0.x + k0.x, q0.y + k0.y, q0.z + k0.z, q0.w + k0.w,
                       q1.x + k1.x, q1.y + k1.y, q1.z + k1.z, q1.w + k1.w};
        float ew[8], eb[8];
        #pragma unroll
        for (int p = 0; p < 4; p++) {
            float2 u = upk2(acc[i][p]);
            ew[2 * p] = u.x; ew[2 * p + 1] = u.y;
            float2 v = upk2(acc[i][4 + p]);
            eb[2 * p] = v.x; eb[2 * p + 1] = v.y;
        }
        float conn[8];
        #pragma unroll
        for (int j = 0; j < 8; j++) {
            float c1 = qk[j] * (ew[j] + ebS[tx * 8 + j]);
            float c2 = copysignf(sqrtf(fabsf(c1)), c1);
            conn[j] = fmaxf(c2 + (eb[j] + ebS[64 + tx * 8 + j]), 0.f);
        }
        float* co = &conn_out[(long long)e * 64 + tx * 8];
        *(float4*)co = make_float4(conn[0], conn[1], conn[2], conn[3]);
        *(float4*)(co + 4) = make_float4(conn[4], conn[5], conn[6], conn[7]);
        float sc = 0.f;
        #pragma unroll
        for (int j = 0; j < 8; j++) sc = fmaf(conn[j], awS[j * 8 + tx], sc);
        sc = fminf(fmaxf(sc, -CLAMP_V), CLAMP_V);
        g_w[e * 8 + tx] = expf(sc);
    }
}

// ---------------- kernel 3: per-node aggregation (warp per node) ----------------
__global__ __launch_bounds__(256) void node_kernel(
    const float* __restrict__ conn_out, const int* __restrict__ eidx,
    const float* __restrict__ Bw, float* __restrict__ No)
{
    __shared__ float bwS[512];
    int tid = threadIdx.x;
    bwS[tid] = Bw[tid];
    bwS[tid + 256] = Bw[tid + 256];
    __syncthreads();

    const int warp = tid >> 5, lane = tid & 31;
    const int n = blockIdx.x * 8 + warp;
    const int j0 = g_off[n], j1 = g_off[n + 1];
    const int h0 = lane >> 3, h1 = h0 + 4, c = lane & 7, base = lane & 24;
    const int* srcArr = eidx + N_EDGES;

    float s0 = 0.f, s1 = 0.f, agg0 = 0.f, agg1 = 0.f, rv0 = 0.f, rv1 = 0.f;
    int e = (j0 < j1) ? g_order[j0] : 0;
    for (int j = j0; j < j1; j++) {
        int e_next = (j + 1 < j1) ? g_order[j + 1] : 0;  // prefetch: breaks dep chain
        int src = srcArr[e];
        float w0 = g_w[e * 8 + h0];
        float w1 = g_w[e * 8 + h1];
        float c0 = conn_out[(long long)e * 64 + lane];
        float c1 = conn_out[(long long)e * 64 + 32 + lane];
        float v0 = g_V[src * 64 + lane];
        float v1 = g_V[src * 64 + 32 + lane];
        s0 += w0; s1 += w1;
        agg0 = fmaf(w0, v0, agg0); rv0 = fmaf(w0, c0, rv0);
        agg1 = fmaf(w1, v1, agg1); rv1 = fmaf(w1, c1, rv1);
        e = e_next;
    }
    float inv0 = (s0 > 0.f) ? 1.f / s0 : 0.f;
    float inv1 = (s1 > 0.f) ? 1.f / s1 : 0.f;
    float rn0 = rv0 * inv0, rn1 = rv1 * inv1;
    float o0 = 0.f, o1 = 0.f;
    #pragma unroll
    for (int d = 0; d < 8; d++) {
        float r0 = __shfl_sync(0xffffffffu, rn0, base + d);
        float r1 = __shfl_sync(0xffffffffu, rn1, base + d);
        o0 = fmaf(r0, bwS[d * 64 + h0 * 8 + c], o0);
        o1 = fmaf(r1, bwS[d * 64 + h1 * 8 + c], o1);
    }
    No[n * 64 + lane] = fmaf(agg0, inv0, o0);
    No[n * 64 + 32 + lane] = fmaf(agg1, inv1, o1);
}

// ---------------- launch ----------------
extern "C" void kernel_launch(void* const* d_in, const int* in_sizes, int n_in,
                              void* d_out, int out_size)
{
    const float* x       = (const float*)d_in[0];
    const float* cf      = (const float*)d_in[1];
    const int*   eidx    = (const int*)d_in[2];
    const float* qkvW    = (const float*)d_in[3];
    const float* qkvB    = (const float*)d_in[4];
    const float* EW      = (const float*)d_in[5];
    const float* EB      = (const float*)d_in[6];
    const float* Aw      = (const float*)d_in[7];
    const float* Bw      = (const float*)d_in[8];

    float* No = (float*)d_out;
    float* conn_out = No + (size_t)N_NODES * 64;

    const int edge_smem = (128 * 68 + 64 * 132 + 64 + 128) * 4 + 256 * 4;
    cudaFuncSetAttribute(edge_kernel, cudaFuncAttributeMaxDynamicSharedMemorySize, edge_smem);

    // ncu (-s 5 -c 1) profiles OUR 4th launch (harness pre-issues ~2).
    // Keep edge_kernel there. Dependencies: edge needs only qkv;
    // node needs edge + scatter; scanC -> scatter.
    zero_kernel<<<(N_NODES + 255) / 256, 256>>>();                         // 1
    qkv_kernel<<<dim3((N_NODES + 63) / 64, 3), 256>>>(x, qkvW, qkvB);      // 2
    count_kernel<<<(N_EDGES + 255) / 256, 256>>>(eidx);                    // 3
    edge_kernel<<<N_EDGES / 128, 256, edge_smem>>>(cf, EW, EB, eidx, Aw, conn_out); // 4 <- profiled
    scanA_kernel<<<SCAN_BLK, 256>>>();                                     // 5
    scanB_kernel<<<1, 256>>>();                                            // 6
    scanC_kernel<<<SCAN_BLK, 256>>>();                                     // 7
    scatter_kernel<<<(N_EDGES + 255) / 256, 256>>>(eidx);                  // 8
    node_kernel<<<N_NODES / 8, 256>>>(conn_out, eidx, Bw, No);             // 9
}

// round 5
// speedup vs baseline: 1.2354x; 1.1857x over previous
#include <cuda_runtime.h>
#include <cuda_bf16.h>

#define N_NODES 50000
#define N_EDGES 800000
#define HEADS 8
#define ADIM 8
#define HD 64            // HEADS*ADIM
#define CLAMP_V 5.0f
#define SCAN_BLK 196     // ceil(50000/256)

// ---------------- scratch (device globals: allocation-free rule) ----------------
__device__ __align__(16) float g_Q[N_NODES * HD];
__device__ __align__(16) float g_K[N_NODES * HD];
__device__ __align__(16) float g_V[N_NODES * HD];
__device__ __align__(16) float g_w[N_EDGES * HEADS];   // exp(clamped score)
__device__ int g_count[N_NODES];
__device__ int g_off[N_NODES + 1];
__device__ int g_cursor[N_NODES];
__device__ int g_order[N_EDGES];
__device__ int g_bsum[SCAN_BLK];
__device__ int g_boff[SCAN_BLK];

// ---------------- f32x2 packed FMA helpers (FFMA2) ----------------
__device__ __forceinline__ unsigned long long pk2(float lo, float hi) {
    unsigned long long r;
    asm("mov.b64 %0, {%1, %2};" : "=l"(r) : "f"(lo), "f"(hi));
    return r;
}
__device__ __forceinline__ void fma2(unsigned long long& d, unsigned long long a, unsigned long long b) {
    asm("fma.rn.f32x2 %0, %1, %2, %0;" : "+l"(d) : "l"(a), "l"(b));
}
__device__ __forceinline__ float2 upk2(unsigned long long v) {
    float lo, hi;
    asm("mov.b64 {%0, %1}, %2;" : "=f"(lo), "=f"(hi) : "l"(v));
    return make_float2(lo, hi);
}

// chunk swizzle for wS: float4-chunk c -> c ^ ((c>>3)&1).
// Makes the 8 chunks read by each quarter-warp land on 8 distinct bank
// groups (was 2-way conflicted at stride 32B). Verified for all 4 loads.
__device__ __forceinline__ int swzc(int c) { return c ^ ((c >> 3) & 1); }

// ---------------- kernel 1: QKV = x @ qkv_weight.T + bias ----------------
__global__ __launch_bounds__(256) void qkv_kernel(
    const float* __restrict__ x, const float* __restrict__ W, const float* __restrict__ bias)
{
    __shared__ float xS[64 * 68];
    __shared__ float wS[64 * 68];   // wS[k*68 + c] = W[(part*64+c)*64 + k]
    const int part = blockIdx.y;
    const int row0 = blockIdx.x * 64;
    const int tid = threadIdx.x;

    #pragma unroll
    for (int p = 0; p < 4; p++) {
        int idx = tid + p * 256;         // float4 index into 64x64 tile
        int r = idx >> 4, c4 = idx & 15;
        float4 v = make_float4(0.f, 0.f, 0.f, 0.f);
        int gr = row0 + r;
        if (gr < N_NODES) v = ((const float4*)x)[gr * 16 + c4];
        *(float4*)&xS[r * 68 + c4 * 4] = v;
    }
    #pragma unroll
    for (int p = 0; p < 4; p++) {
        int idx = tid + p * 256;
        int c = idx >> 4, f = idx & 15;
        float4 v = ((const float4*)W)[(part * 64 + c) * 16 + f];
        wS[(f * 4 + 0) * 68 + c] = v.x;
        wS[(f * 4 + 1) * 68 + c] = v.y;
        wS[(f * 4 + 2) * 68 + c] = v.z;
        wS[(f * 4 + 3) * 68 + c] = v.w;
    }
    __syncthreads();

    const int tx = tid & 15, ty = tid >> 4;   // 4 cols x 4 rows per thread
    unsigned long long acc[4][2];
    #pragma unroll
    for (int i = 0; i < 4; i++) { acc[i][0] = 0ull; acc[i][1] = 0ull; }

    #pragma unroll 4
    for (int k = 0; k < 64; k++) {
        float4 b = *(float4*)&wS[k * 68 + tx * 4];
        unsigned long long b0 = pk2(b.x, b.y), b1 = pk2(b.z, b.w);
        #pragma unroll
        for (int i = 0; i < 4; i++) {
            float a = xS[(ty * 4 + i) * 68 + k];
            unsigned long long a2 = pk2(a, a);
            fma2(acc[i][0], a2, b0);
            fma2(acc[i][1], a2, b1);
        }
    }

    float* outBase = (part == 0) ? g_Q : (part == 1 ? g_K : g_V);
    float4 bv = ((const float4*)bias)[part * 16 + tx];
    #pragma unroll
    for (int i = 0; i < 4; i++) {
        int gr = row0 + ty * 4 + i;
        if (gr < N_NODES) {
            float2 p0 = upk2(acc[i][0]), p1 = upk2(acc[i][1]);
            float4 o = make_float4(p0.x + bv.x, p0.y + bv.y, p1.x + bv.z, p1.y + bv.w);
            *(float4*)&outBase[gr * 64 + tx * 4] = o;
        }
    }
}

// ---------------- CSR construction ----------------
__global__ void zero_kernel() {
    int i = blockIdx.x * blockDim.x + threadIdx.x;
    if (i < N_NODES) g_count[i] = 0;
}
__global__ void count_kernel(const int* __restrict__ eidx) {
    int e = blockIdx.x * blockDim.x + threadIdx.x;
    if (e < N_EDGES) atomicAdd(&g_count[eidx[e]], 1);
}

// phase A: per-block sums of g_count (196 blocks x 256 threads)
__global__ __launch_bounds__(256) void scanA_kernel() {
    __shared__ int ws[8];
    int t = threadIdx.x, i = blockIdx.x * 256 + t;
    int v = (i < N_NODES) ? g_count[i] : 0;
    #pragma unroll
    for (int o = 16; o > 0; o >>= 1) v += __shfl_down_sync(0xffffffffu, v, o);
    if ((t & 31) == 0) ws[t >> 5] = v;
    __syncthreads();
    if (t == 0) {
        int s = 0;
        #pragma unroll
        for (int w = 0; w < 8; w++) s += ws[w];
        g_bsum[blockIdx.x] = s;
    }
}
// phase B: exclusive scan over 196 partials (1 block)
__global__ __launch_bounds__(256) void scanB_kernel() {
    __shared__ int ws[8];
    int t = threadIdx.x, lane = t & 31, w = t >> 5;
    int v = (t < SCAN_BLK) ? g_bsum[t] : 0;
    int x = v;
    #pragma unroll
    for (int o = 1; o < 32; o <<= 1) {
        int y = __shfl_up_sync(0xffffffffu, x, o);
        if (lane >= o) x += y;
    }
    if (lane == 31) ws[w] = x;
    __syncthreads();
    if (t == 0) {
        int run = 0;
        #pragma unroll
        for (int k = 0; k < 8; k++) { int tmp = ws[k]; ws[k] = run; run += tmp; }
    }
    __syncthreads();
    if (t < SCAN_BLK) g_boff[t] = x - v + ws[w];
    if (t == 0) g_off[N_NODES] = N_EDGES;
}
// phase C: local exclusive scan + block offset -> g_off / g_cursor
__global__ __launch_bounds__(256) void scanC_kernel() {
    __shared__ int ws[8];
    int t = threadIdx.x, lane = t & 31, w = t >> 5;
    int i = blockIdx.x * 256 + t;
    int v = (i < N_NODES) ? g_count[i] : 0;
    int x = v;
    #pragma unroll
    for (int o = 1; o < 32; o <<= 1) {
        int y = __shfl_up_sync(0xffffffffu, x, o);
        if (lane >= o) x += y;
    }
    if (lane == 31) ws[w] = x;
    __syncthreads();
    if (t == 0) {
        int run = 0;
        #pragma unroll
        for (int k = 0; k < 8; k++) { int tmp = ws[k]; ws[k] = run; run += tmp; }
    }
    __syncthreads();
    if (i < N_NODES) {
        int excl = x - v + ws[w] + g_boff[blockIdx.x];
        g_off[i] = excl;
        g_cursor[i] = excl;
    }
}
__global__ void scatter_kernel(const int* __restrict__ eidx) {
    int e = blockIdx.x * blockDim.x + threadIdx.x;
    if (e < N_EDGES) {
        int dst = eidx[e];
        int pos = atomicAdd(&g_cursor[dst], 1);
        g_order[pos] = e;
    }
}

// ---------------- kernel 2: fused edge GEMM + conn + score ----------------
// block = 128 edges, 256 threads. thread = 4 edges x 1 head x {Ew(8), Eb(8)}.
// wS rows are chunk-swizzled (swzc) to kill the 2-way bank conflict on the
// stride-32B weight loads (L1 crossbar was 95% = the bottleneck).
__global__ __launch_bounds__(256) void edge_kernel(
    const float* __restrict__ cf, const float* __restrict__ EW,
    const float* __restrict__ Ebias, const int* __restrict__ eidx,
    const float* __restrict__ Aw, float* __restrict__ conn_out)
{
    extern __shared__ float sm[];
    float* cfS = sm;                      // 128*68
    float* wS = cfS + 128 * 68;           // 64*132 : row k holds swizzled EW^T row
    float* awS = wS + 64 * 132;           // 64
    float* ebS = awS + 64;                // 128
    int* sDst = (int*)(ebS + 128);        // 128
    int* sSrc = sDst + 128;               // 128

    const int tid = threadIdx.x;
    const int e0 = blockIdx.x * 128;

    #pragma unroll
    for (int p = 0; p < 8; p++) {
        int idx = tid + p * 256;          // float4 index over 128x64 cf tile
        int r = idx >> 4, c4 = idx & 15;
        float4 v = ((const float4*)cf)[(e0 + r) * 16 + c4];
        *(float4*)&cfS[r * 68 + c4 * 4] = v;
    }
    #pragma unroll
    for (int p = 0; p < 8; p++) {
        int idx = tid + p * 256;          // float4 index over 128x64 EW
        int n = idx >> 4, f = idx & 15;   // n = output col (0..127), f = k-chunk
        float4 v = ((const float4*)EW)[n * 16 + f];
        int pos = (swzc(n >> 2) << 2) | (n & 3);   // swizzled float index in row
        wS[(f * 4 + 0) * 132 + pos] = v.x;
        wS[(f * 4 + 1) * 132 + pos] = v.y;
        wS[(f * 4 + 2) * 132 + pos] = v.z;
        wS[(f * 4 + 3) * 132 + pos] = v.w;
    }
    if (tid < 64) awS[tid] = Aw[tid];
    if (tid >= 64 && tid < 192) ebS[tid - 64] = Ebias[tid - 64];
    if (tid < 128) {
        sDst[tid] = eidx[e0 + tid];
        sSrc[tid] = eidx[N_EDGES + e0 + tid];
    }
    __syncthreads();

    const int tx = tid & 7;               // head
    const int tg = tid >> 3;              // edge group (4 edges)

    // precomputed swizzled chunk offsets (in floats) for the 4 weight loads
    const int o0 = swzc(tx * 2) * 4;          // Ew lo  (cols tx*8 .. +3)
    const int o1 = swzc(tx * 2 + 1) * 4;      // Ew hi  (cols tx*8+4 .. +7)
    const int o2 = swzc(16 + tx * 2) * 4;     // Eb lo
    const int o3 = swzc(16 + tx * 2 + 1) * 4; // Eb hi

    unsigned long long acc[4][8];
    #pragma unroll
    for (int i = 0; i < 4; i++)
        #pragma unroll
        for (int p = 0; p < 8; p++) acc[i][p] = 0ull;

    #pragma unroll 1
    for (int k4 = 0; k4 < 64; k4 += 4) {
        // 4 edges x 4 k-values in one vector load each
        float4 a4[4];
        #pragma unroll
        for (int i = 0; i < 4; i++)
            a4[i] = *(const float4*)&cfS[(tg * 4 + i) * 68 + k4];

        #pragma unroll
        for (int kk = 0; kk < 4; kk++) {
            const float* wr = &wS[(k4 + kk) * 132];
            float4 w0 = *(const float4*)&wr[o0];
            float4 w1 = *(const float4*)&wr[o1];
            float4 w2 = *(const float4*)&wr[o2];
            float4 w3 = *(const float4*)&wr[o3];
            unsigned long long b[8];
            b[0] = pk2(w0.x, w0.y); b[1] = pk2(w0.z, w0.w);
            b[2] = pk2(w1.x, w1.y); b[3] = pk2(w1.z, w1.w);
            b[4] = pk2(w2.x, w2.y); b[5] = pk2(w2.z, w2.w);
            b[6] = pk2(w3.x, w3.y); b[7] = pk2(w3.z, w3.w);
            #pragma unroll
            for (int i = 0; i < 4; i++) {
                float a = (kk == 0) ? a4[i].x : (kk == 1) ? a4[i].y
                        : (kk == 2) ? a4[i].z : a4[i].w;
                unsigned long long a2 = pk2(a, a);
                #pragma unroll
                for (int p = 0; p < 8; p++) fma2(acc[i][p], a2, b[p]);
            }
        }
    }

    // epilogue per edge: conn1 -> signed sqrt -> +Eb -> relu -> write; score -> w
    #pragma unroll
    for (int i = 0; i < 4; i++) {
        int el = tg * 4 + i;
        int e = e0 + el;
        int d = sDst[el], s = sSrc[el];
        float4 q0 = ((const float4*)g_Q)[d * 16 + tx * 2];
        float4 q1 = ((const float4*)g_Q)[d * 16 + tx * 2 + 1];
        float4 k0 = ((const float4*)g_K)[s * 16 + tx * 2];
        float4 k1 = ((const float4*)g_K)[s * 16 + tx * 2 + 1];
        float qk[8] = {q0.x + k0.x, q0.y + k0.y, q0.z + k0.z, q0.w + k0.w,
                       q1.x + k1.x, q1.y + k1.y, q1.z + k1.z, q1.w + k1.w};
        float ew[8], eb[8];
        #pragma unroll
        for (int p = 0; p < 4; p++) {
            float2 u = upk2(acc[i][p]);
            ew[2 * p] = u.x; ew[2 * p + 1] = u.y;
            float2 v = upk2(acc[i][4 + p]);
            eb[2 * p] = v.x; eb[2 * p + 1] = v.y;
        }
        float conn[8];
        #pragma unroll
        for (int j = 0; j < 8; j++) {
            float c1 = qk[j] * (ew[j] + ebS[tx * 8 + j]);
            float c2 = copysignf(sqrtf(fabsf(c1)), c1);
            conn[j] = fmaxf(c2 + (eb[j] + ebS[64 + tx * 8 + j]), 0.f);
        }
        float* co = &conn_out[(long long)e * 64 + tx * 8];
        *(float4*)co = make_float4(conn[0], conn[1], conn[2], conn[3]);
        *(float4*)(co + 4) = make_float4(conn[4], conn[5], conn[6], conn[7]);
        float sc = 0.f;
        #pragma unroll
        for (int j = 0; j < 8; j++) sc = fmaf(conn[j], awS[j * 8 + tx], sc);
        sc = fminf(fmaxf(sc, -CLAMP_V), CLAMP_V);
        g_w[e * 8 + tx] = expf(sc);
    }
}

// ---------------- kernel 3: per-node aggregation (warp per node) ----------------
__global__ __launch_bounds__(256) void node_kernel(
    const float* __restrict__ conn_out, const int* __restrict__ eidx,
    const float* __restrict__ Bw, float* __restrict__ No)
{
    __shared__ float bwS[512];
    int tid = threadIdx.x;
    bwS[tid] = Bw[tid];
    bwS[tid + 256] = Bw[tid + 256];
    __syncthreads();

    const int warp = tid >> 5, lane = tid & 31;
    const int n = blockIdx.x * 8 + warp;
    const int j0 = g_off[n], j1 = g_off[n + 1];
    const int h0 = lane >> 3, h1 = h0 + 4, c = lane & 7, base = lane & 24;
    const int* srcArr = eidx + N_EDGES;

    float s0 = 0.f, s1 = 0.f, agg0 = 0.f, agg1 = 0.f, rv0 = 0.f, rv1 = 0.f;
    int e = (j0 < j1) ? g_order[j0] : 0;
    for (int j = j0; j < j1; j++) {
        int e_next = (j + 1 < j1) ? g_order[j + 1] : 0;  // prefetch: breaks dep chain
        int src = srcArr[e];
        float w0 = g_w[e * 8 + h0];
        float w1 = g_w[e * 8 + h1];
        float c0 = conn_out[(long long)e * 64 + lane];
        float c1 = conn_out[(long long)e * 64 + 32 + lane];
        float v0 = g_V[src * 64 + lane];
        float v1 = g_V[src * 64 + 32 + lane];
        s0 += w0; s1 += w1;
        agg0 = fmaf(w0, v0, agg0); rv0 = fmaf(w0, c0, rv0);
        agg1 = fmaf(w1, v1, agg1); rv1 = fmaf(w1, c1, rv1);
        e = e_next;
    }
    float inv0 = (s0 > 0.f) ? 1.f / s0 : 0.f;
    float inv1 = (s1 > 0.f) ? 1.f / s1 : 0.f;
    float rn0 = rv0 * inv0, rn1 = rv1 * inv1;
    float o0 = 0.f, o1 = 0.f;
    #pragma unroll
    for (int d = 0; d < 8; d++) {
        float r0 = __shfl_sync(0xffffffffu, rn0, base + d);
        float r1 = __shfl_sync(0xffffffffu, rn1, base + d);
        o0 = fmaf(r0, bwS[d * 64 + h0 * 8 + c], o0);
        o1 = fmaf(r1, bwS[d * 64 + h1 * 8 + c], o1);
    }
    No[n * 64 + lane] = fmaf(agg0, inv0, o0);
    No[n * 64 + 32 + lane] = fmaf(agg1, inv1, o1);
}

// ---------------- launch ----------------
extern "C" void kernel_launch(void* const* d_in, const int* in_sizes, int n_in,
                              void* d_out, int out_size)
{
    const float* x       = (const float*)d_in[0];
    const float* cf      = (const float*)d_in[1];
    const int*   eidx    = (const int*)d_in[2];
    const float* qkvW    = (const float*)d_in[3];
    const float* qkvB    = (const float*)d_in[4];
    const float* EW      = (const float*)d_in[5];
    const float* EB      = (const float*)d_in[6];
    const float* Aw      = (const float*)d_in[7];
    const float* Bw      = (const float*)d_in[8];

    float* No = (float*)d_out;
    float* conn_out = No + (size_t)N_NODES * 64;

    const int edge_smem = (128 * 68 + 64 * 132 + 64 + 128) * 4 + 256 * 4;
    cudaFuncSetAttribute(edge_kernel, cudaFuncAttributeMaxDynamicSharedMemorySize, edge_smem);

    // ncu (-s 5 -c 1) profiles OUR 4th launch (harness pre-issues ~2).
    // Keep edge_kernel there. Dependencies: edge needs only qkv;
    // node needs edge + scatter; scanC -> scatter.
    zero_kernel<<<(N_NODES + 255) / 256, 256>>>();                         // 1
    qkv_kernel<<<dim3((N_NODES + 63) / 64, 3), 256>>>(x, qkvW, qkvB);      // 2
    count_kernel<<<(N_EDGES + 255) / 256, 256>>>(eidx);                    // 3
    edge_kernel<<<N_EDGES / 128, 256, edge_smem>>>(cf, EW, EB, eidx, Aw, conn_out); // 4 <- profiled
    scanA_kernel<<<SCAN_BLK, 256>>>();                                     // 5
    scanB_kernel<<<1, 256>>>();                                            // 6
    scanC_kernel<<<SCAN_BLK, 256>>>();                                     // 7
    scatter_kernel<<<(N_EDGES + 255) / 256, 256>>>(eidx);                  // 8
    node_kernel<<<N_NODES / 8, 256>>>(conn_out, eidx, Bw, No);             // 9
}

// round 6
// speedup vs baseline: 1.3036x; 1.0552x over previous
#include <cuda_runtime.h>
#include <cuda_bf16.h>

#define N_NODES 50000
#define N_EDGES 800000
#define HEADS 8
#define ADIM 8
#define HD 64            // HEADS*ADIM
#define CLAMP_V 5.0f
#define SCAN_BLK 196     // ceil(50000/256)

// ---------------- scratch (device globals: allocation-free rule) ----------------
__device__ __align__(16) float g_Q[N_NODES * HD];
__device__ __align__(16) float g_K[N_NODES * HD];
__device__ __align__(16) float g_V[N_NODES * HD];
__device__ __align__(16) float g_w[N_EDGES * HEADS];   // exp(clamped score)
__device__ int g_count[N_NODES];
__device__ int g_off[N_NODES + 1];
__device__ int g_cursor[N_NODES];
__device__ int g_order[N_EDGES];
__device__ int g_bsum[SCAN_BLK];
__device__ int g_boff[SCAN_BLK];

// ---------------- f32x2 packed FMA helpers (FFMA2) ----------------
__device__ __forceinline__ unsigned long long pk2(float lo, float hi) {
    unsigned long long r;
    asm("mov.b64 %0, {%1, %2};" : "=l"(r) : "f"(lo), "f"(hi));
    return r;
}
__device__ __forceinline__ void fma2(unsigned long long& d, unsigned long long a, unsigned long long b) {
    asm("fma.rn.f32x2 %0, %1, %2, %0;" : "+l"(d) : "l"(a), "l"(b));
}
__device__ __forceinline__ float2 upk2(unsigned long long v) {
    float lo, hi;
    asm("mov.b64 {%0, %1}, %2;" : "=f"(lo), "=f"(hi) : "l"(v));
    return make_float2(lo, hi);
}

// chunk swizzle for wS: float4-chunk c -> c ^ ((c>>3)&1).
// Conflict-free for both the 16-chunk-stride reads and the 8x8 mapping's
// per-quarter chunk reads (verified per lane group).
__device__ __forceinline__ int swzc(int c) { return c ^ ((c >> 3) & 1); }

// ---------------- kernel 1: QKV = x @ qkv_weight.T + bias ----------------
__global__ __launch_bounds__(256) void qkv_kernel(
    const float* __restrict__ x, const float* __restrict__ W, const float* __restrict__ bias)
{
    __shared__ float xS[64 * 68];
    __shared__ float wS[64 * 68];   // wS[k*68 + c] = W[(part*64+c)*64 + k]
    const int part = blockIdx.y;
    const int row0 = blockIdx.x * 64;
    const int tid = threadIdx.x;

    #pragma unroll
    for (int p = 0; p < 4; p++) {
        int idx = tid + p * 256;         // float4 index into 64x64 tile
        int r = idx >> 4, c4 = idx & 15;
        float4 v = make_float4(0.f, 0.f, 0.f, 0.f);
        int gr = row0 + r;
        if (gr < N_NODES) v = ((const float4*)x)[gr * 16 + c4];
        *(float4*)&xS[r * 68 + c4 * 4] = v;
    }
    #pragma unroll
    for (int p = 0; p < 4; p++) {
        int idx = tid + p * 256;
        int c = idx >> 4, f = idx & 15;
        float4 v = ((const float4*)W)[(part * 64 + c) * 16 + f];
        wS[(f * 4 + 0) * 68 + c] = v.x;
        wS[(f * 4 + 1) * 68 + c] = v.y;
        wS[(f * 4 + 2) * 68 + c] = v.z;
        wS[(f * 4 + 3) * 68 + c] = v.w;
    }
    __syncthreads();

    const int tx = tid & 15, ty = tid >> 4;   // 4 cols x 4 rows per thread
    unsigned long long acc[4][2];
    #pragma unroll
    for (int i = 0; i < 4; i++) { acc[i][0] = 0ull; acc[i][1] = 0ull; }

    #pragma unroll 4
    for (int k = 0; k < 64; k++) {
        float4 b = *(float4*)&wS[k * 68 + tx * 4];
        unsigned long long b0 = pk2(b.x, b.y), b1 = pk2(b.z, b.w);
        #pragma unroll
        for (int i = 0; i < 4; i++) {
            float a = xS[(ty * 4 + i) * 68 + k];
            unsigned long long a2 = pk2(a, a);
            fma2(acc[i][0], a2, b0);
            fma2(acc[i][1], a2, b1);
        }
    }

    float* outBase = (part == 0) ? g_Q : (part == 1 ? g_K : g_V);
    float4 bv = ((const float4*)bias)[part * 16 + tx];
    #pragma unroll
    for (int i = 0; i < 4; i++) {
        int gr = row0 + ty * 4 + i;
        if (gr < N_NODES) {
            float2 p0 = upk2(acc[i][0]), p1 = upk2(acc[i][1]);
            float4 o = make_float4(p0.x + bv.x, p0.y + bv.y, p1.x + bv.z, p1.y + bv.w);
            *(float4*)&outBase[gr * 64 + tx * 4] = o;
        }
    }
}

// ---------------- CSR construction ----------------
__global__ void zero_kernel() {
    int i = blockIdx.x * blockDim.x + threadIdx.x;
    if (i < N_NODES) g_count[i] = 0;
}
__global__ void count_kernel(const int* __restrict__ eidx) {
    int e = blockIdx.x * blockDim.x + threadIdx.x;
    if (e < N_EDGES) atomicAdd(&g_count[eidx[e]], 1);
}

// phase A: per-block sums of g_count (196 blocks x 256 threads)
__global__ __launch_bounds__(256) void scanA_kernel() {
    __shared__ int ws[8];
    int t = threadIdx.x, i = blockIdx.x * 256 + t;
    int v = (i < N_NODES) ? g_count[i] : 0;
    #pragma unroll
    for (int o = 16; o > 0; o >>= 1) v += __shfl_down_sync(0xffffffffu, v, o);
    if ((t & 31) == 0) ws[t >> 5] = v;
    __syncthreads();
    if (t == 0) {
        int s = 0;
        #pragma unroll
        for (int w = 0; w < 8; w++) s += ws[w];
        g_bsum[blockIdx.x] = s;
    }
}
// phase B: exclusive scan over 196 partials (1 block)
__global__ __launch_bounds__(256) void scanB_kernel() {
    __shared__ int ws[8];
    int t = threadIdx.x, lane = t & 31, w = t >> 5;
    int v = (t < SCAN_BLK) ? g_bsum[t] : 0;
    int x = v;
    #pragma unroll
    for (int o = 1; o < 32; o <<= 1) {
        int y = __shfl_up_sync(0xffffffffu, x, o);
        if (lane >= o) x += y;
    }
    if (lane == 31) ws[w] = x;
    __syncthreads();
    if (t == 0) {
        int run = 0;
        #pragma unroll
        for (int k = 0; k < 8; k++) { int tmp = ws[k]; ws[k] = run; run += tmp; }
    }
    __syncthreads();
    if (t < SCAN_BLK) g_boff[t] = x - v + ws[w];
    if (t == 0) g_off[N_NODES] = N_EDGES;
}
// phase C: local exclusive scan + block offset -> g_off / g_cursor
__global__ __launch_bounds__(256) void scanC_kernel() {
    __shared__ int ws[8];
    int t = threadIdx.x, lane = t & 31, w = t >> 5;
    int i = blockIdx.x * 256 + t;
    int v = (i < N_NODES) ? g_count[i] : 0;
    int x = v;
    #pragma unroll
    for (int o = 1; o < 32; o <<= 1) {
        int y = __shfl_up_sync(0xffffffffu, x, o);
        if (lane >= o) x += y;
    }
    if (lane == 31) ws[w] = x;
    __syncthreads();
    if (t == 0) {
        int run = 0;
        #pragma unroll
        for (int k = 0; k < 8; k++) { int tmp = ws[k]; ws[k] = run; run += tmp; }
    }
    __syncthreads();
    if (i < N_NODES) {
        int excl = x - v + ws[w] + g_boff[blockIdx.x];
        g_off[i] = excl;
        g_cursor[i] = excl;
    }
}
__global__ void scatter_kernel(const int* __restrict__ eidx) {
    int e = blockIdx.x * blockDim.x + threadIdx.x;
    if (e < N_EDGES) {
        int dst = eidx[e];
        int pos = atomicAdd(&g_cursor[dst], 1);
        g_order[pos] = e;
    }
}

// ---------------- kernel 2: fused edge GEMM + conn + score ----------------
// block = 128 edges, 256 threads. NEW thread tile = 8 edges x 8 cols
// (4 Ew + 4 Eb of one head-half): 64B operands per 64 FMAs per k
// (was 80B with 4x16) -> crossbar phases 20 -> 16 per warp-k.
//   tx4 = tid & 15 : col chunk (head h = tx4>>1, dims (tx4&1)*4..+3)
//   tg  = tid >> 4 : edge group (8 edges)
__global__ __launch_bounds__(256) void edge_kernel(
    const float* __restrict__ cf, const float* __restrict__ EW,
    const float* __restrict__ Ebias, const int* __restrict__ eidx,
    const float* __restrict__ Aw, float* __restrict__ conn_out)
{
    extern __shared__ float sm[];
    float* cfS = sm;                      // 128*68
    float* wS = cfS + 128 * 68;           // 64*132 : row k holds swizzled EW^T row
    float* awS = wS + 64 * 132;           // 64
    float* ebS = awS + 64;                // 128
    int* sDst = (int*)(ebS + 128);        // 128
    int* sSrc = sDst + 128;               // 128

    const int tid = threadIdx.x;
    const int e0 = blockIdx.x * 128;

    #pragma unroll
    for (int p = 0; p < 8; p++) {
        int idx = tid + p * 256;          // float4 index over 128x64 cf tile
        int r = idx >> 4, c4 = idx & 15;
        float4 v = ((const float4*)cf)[(e0 + r) * 16 + c4];
        *(float4*)&cfS[r * 68 + c4 * 4] = v;
    }
    #pragma unroll
    for (int p = 0; p < 8; p++) {
        int idx = tid + p * 256;          // float4 index over 128x64 EW
        int n = idx >> 4, f = idx & 15;   // n = output col (0..127), f = k-chunk
        float4 v = ((const float4*)EW)[n * 16 + f];
        int pos = (swzc(n >> 2) << 2) | (n & 3);   // swizzled float index in row
        wS[(f * 4 + 0) * 132 + pos] = v.x;
        wS[(f * 4 + 1) * 132 + pos] = v.y;
        wS[(f * 4 + 2) * 132 + pos] = v.z;
        wS[(f * 4 + 3) * 132 + pos] = v.w;
    }
    if (tid < 64) awS[tid] = Aw[tid];
    if (tid >= 64 && tid < 192) ebS[tid - 64] = Ebias[tid - 64];
    if (tid < 128) {
        sDst[tid] = eidx[e0 + tid];
        sSrc[tid] = eidx[N_EDGES + e0 + tid];
    }
    __syncthreads();

    const int tx4 = tid & 15;             // col chunk
    const int tg = tid >> 4;              // edge group (8 edges)
    const int h = tx4 >> 1;               // head
    const int dimb = (tx4 & 1) * 4;       // dim base within head

    // swizzled chunk offsets (floats) for the two weight loads
    const int oE = swzc(tx4) * 4;          // Ew cols tx4*4..+3
    const int oB = swzc(16 + tx4) * 4;     // Eb cols tx4*4..+3

    // acc[edge][0..1] = Ew pair, [2..3] = Eb pair
    unsigned long long acc[8][4];
    #pragma unroll
    for (int j = 0; j < 8; j++)
        #pragma unroll
        for (int p = 0; p < 4; p++) acc[j][p] = 0ull;

    #pragma unroll 1
    for (int k4 = 0; k4 < 64; k4 += 4) {
        // 8 edges x 4 k-values (one LDS.128 each, quarter-warp broadcast)
        float4 a4[8];
        #pragma unroll
        for (int j = 0; j < 8; j++)
            a4[j] = *(const float4*)&cfS[(tg * 8 + j) * 68 + k4];

        #pragma unroll
        for (int kk = 0; kk < 4; kk++) {
            const float* wr = &wS[(k4 + kk) * 132];
            float4 wE = *(const float4*)&wr[oE];
            float4 wB = *(const float4*)&wr[oB];
            unsigned long long b0 = pk2(wE.x, wE.y), b1 = pk2(wE.z, wE.w);
            unsigned long long b2 = pk2(wB.x, wB.y), b3 = pk2(wB.z, wB.w);
            #pragma unroll
            for (int j = 0; j < 8; j++) {
                float a = (kk == 0) ? a4[j].x : (kk == 1) ? a4[j].y
                        : (kk == 2) ? a4[j].z : a4[j].w;
                unsigned long long a2 = pk2(a, a);
                fma2(acc[j][0], a2, b0);
                fma2(acc[j][1], a2, b1);
                fma2(acc[j][2], a2, b2);
                fma2(acc[j][3], a2, b3);
            }
        }
    }

    // epilogue: per edge, 4 dims of head h
    const float ebw0 = ebS[tx4 * 4 + 0], ebw1 = ebS[tx4 * 4 + 1];
    const float ebw2 = ebS[tx4 * 4 + 2], ebw3 = ebS[tx4 * 4 + 3];
    const float ebb0 = ebS[64 + tx4 * 4 + 0], ebb1 = ebS[64 + tx4 * 4 + 1];
    const float ebb2 = ebS[64 + tx4 * 4 + 2], ebb3 = ebS[64 + tx4 * 4 + 3];
    const float aw0 = awS[(dimb + 0) * 8 + h], aw1 = awS[(dimb + 1) * 8 + h];
    const float aw2 = awS[(dimb + 2) * 8 + h], aw3 = awS[(dimb + 3) * 8 + h];

    #pragma unroll
    for (int j = 0; j < 8; j++) {
        int el = tg * 8 + j;
        int e = e0 + el;
        int d = sDst[el], s = sSrc[el];
        float4 q = ((const float4*)g_Q)[d * 16 + tx4];
        float4 kk = ((const float4*)g_K)[s * 16 + tx4];
        float qk[4] = {q.x + kk.x, q.y + kk.y, q.z + kk.z, q.w + kk.w};
        float2 e01 = upk2(acc[j][0]), e23 = upk2(acc[j][1]);
        float2 b01 = upk2(acc[j][2]), b23 = upk2(acc[j][3]);
        float ew[4] = {e01.x, e01.y, e23.x, e23.y};
        float eb[4] = {b01.x, b01.y, b23.x, b23.y};
        float ebw[4] = {ebw0, ebw1, ebw2, ebw3};
        float ebb[4] = {ebb0, ebb1, ebb2, ebb3};
        float conn[4];
        #pragma unroll
        for (int m = 0; m < 4; m++) {
            float c1 = qk[m] * (ew[m] + ebw[m]);
            float c2 = copysignf(sqrtf(fabsf(c1)), c1);
            conn[m] = fmaxf(c2 + (eb[m] + ebb[m]), 0.f);
        }
        *(float4*)&conn_out[(long long)e * 64 + tx4 * 4] =
            make_float4(conn[0], conn[1], conn[2], conn[3]);
        float scp = conn[0] * aw0 + conn[1] * aw1 + conn[2] * aw2 + conn[3] * aw3;
        float sc = scp + __shfl_xor_sync(0xffffffffu, scp, 1);
        sc = fminf(fmaxf(sc, -CLAMP_V), CLAMP_V);
        if ((tx4 & 1) == 0) g_w[e * 8 + h] = expf(sc);
    }
}

// ---------------- kernel 3: per-node aggregation (warp per node) ----------------
__global__ __launch_bounds__(256) void node_kernel(
    const float* __restrict__ conn_out, const int* __restrict__ eidx,
    const float* __restrict__ Bw, float* __restrict__ No)
{
    __shared__ float bwS[512];
    int tid = threadIdx.x;
    bwS[tid] = Bw[tid];
    bwS[tid + 256] = Bw[tid + 256];
    __syncthreads();

    const int warp = tid >> 5, lane = tid & 31;
    const int n = blockIdx.x * 8 + warp;
    const int j0 = g_off[n], j1 = g_off[n + 1];
    const int h0 = lane >> 3, h1 = h0 + 4, c = lane & 7, base = lane & 24;
    const int* srcArr = eidx + N_EDGES;

    float s0 = 0.f, s1 = 0.f, agg0 = 0.f, agg1 = 0.f, rv0 = 0.f, rv1 = 0.f;
    int e = (j0 < j1) ? g_order[j0] : 0;
    for (int j = j0; j < j1; j++) {
        int e_next = (j + 1 < j1) ? g_order[j + 1] : 0;  // prefetch: breaks dep chain
        int src = srcArr[e];
        float w0 = g_w[e * 8 + h0];
        float w1 = g_w[e * 8 + h1];
        float c0 = conn_out[(long long)e * 64 + lane];
        float c1 = conn_out[(long long)e * 64 + 32 + lane];
        float v0 = g_V[src * 64 + lane];
        float v1 = g_V[src * 64 + 32 + lane];
        s0 += w0; s1 += w1;
        agg0 = fmaf(w0, v0, agg0); rv0 = fmaf(w0, c0, rv0);
        agg1 = fmaf(w1, v1, agg1); rv1 = fmaf(w1, c1, rv1);
        e = e_next;
    }
    float inv0 = (s0 > 0.f) ? 1.f / s0 : 0.f;
    float inv1 = (s1 > 0.f) ? 1.f / s1 : 0.f;
    float rn0 = rv0 * inv0, rn1 = rv1 * inv1;
    float o0 = 0.f, o1 = 0.f;
    #pragma unroll
    for (int d = 0; d < 8; d++) {
        float r0 = __shfl_sync(0xffffffffu, rn0, base + d);
        float r1 = __shfl_sync(0xffffffffu, rn1, base + d);
        o0 = fmaf(r0, bwS[d * 64 + h0 * 8 + c], o0);
        o1 = fmaf(r1, bwS[d * 64 + h1 * 8 + c], o1);
    }
    No[n * 64 + lane] = fmaf(agg0, inv0, o0);
    No[n * 64 + 32 + lane] = fmaf(agg1, inv1, o1);
}

// ---------------- launch ----------------
extern "C" void kernel_launch(void* const* d_in, const int* in_sizes, int n_in,
                              void* d_out, int out_size)
{
    const float* x       = (const float*)d_in[0];
    const float* cf      = (const float*)d_in[1];
    const int*   eidx    = (const int*)d_in[2];
    const float* qkvW    = (const float*)d_in[3];
    const float* qkvB    = (const float*)d_in[4];
    const float* EW      = (const float*)d_in[5];
    const float* EB      = (const float*)d_in[6];
    const float* Aw      = (const float*)d_in[7];
    const float* Bw      = (const float*)d_in[8];

    float* No = (float*)d_out;
    float* conn_out = No + (size_t)N_NODES * 64;

    const int edge_smem = (128 * 68 + 64 * 132 + 64 + 128) * 4 + 256 * 4;
    cudaFuncSetAttribute(edge_kernel, cudaFuncAttributeMaxDynamicSharedMemorySize, edge_smem);

    // ncu (-s 5 -c 1) profiles OUR 4th launch (harness pre-issues ~2).
    // Keep edge_kernel there. Dependencies: edge needs only qkv;
    // node needs edge + scatter; scanC -> scatter.
    zero_kernel<<<(N_NODES + 255) / 256, 256>>>();                         // 1
    qkv_kernel<<<dim3((N_NODES + 63) / 64, 3), 256>>>(x, qkvW, qkvB);      // 2
    count_kernel<<<(N_EDGES + 255) / 256, 256>>>(eidx);                    // 3
    edge_kernel<<<N_EDGES / 128, 256, edge_smem>>>(cf, EW, EB, eidx, Aw, conn_out); // 4 <- profiled
    scanA_kernel<<<SCAN_BLK, 256>>>();                                     // 5
    scanB_kernel<<<1, 256>>>();                                            // 6
    scanC_kernel<<<SCAN_BLK, 256>>>();                                     // 7
    scatter_kernel<<<(N_EDGES + 255) / 256, 256>>>(eidx);                  // 8
    node_kernel<<<N_NODES / 8, 256>>>(conn_out, eidx, Bw, No);             // 9
}

// round 8
// speedup vs baseline: 1.3942x; 1.0695x over previous
#include <cuda_runtime.h>
#include <cuda_bf16.h>
#include <cstdint>

#define N_NODES 50000
#define N_EDGES 800000
#define HEADS 8
#define ADIM 8
#define HD 64            // HEADS*ADIM
#define CLAMP_V 5.0f
#define SCAN_BLK 196     // ceil(50000/256)

// ---------------- scratch (device globals: allocation-free rule) ----------------
__device__ __align__(16) float g_Q[N_NODES * HD];
__device__ __align__(16) float g_K[N_NODES * HD];
__device__ __align__(16) float g_V[N_NODES * HD];
__device__ __align__(16) float g_w[N_EDGES * HEADS];   // exp(clamped score)
__device__ int g_count[N_NODES];
__device__ int g_off[N_NODES + 1];
__device__ int g_cursor[N_NODES];
__device__ int g_order[N_EDGES];
__device__ int g_bsum[SCAN_BLK];
__device__ int g_boff[SCAN_BLK];

// ---------------- f32x2 packed FMA helpers (qkv kernel) ----------------
__device__ __forceinline__ unsigned long long pk2(float lo, float hi) {
    unsigned long long r;
    asm("mov.b64 %0, {%1, %2};" : "=l"(r) : "f"(lo), "f"(hi));
    return r;
}
__device__ __forceinline__ void fma2(unsigned long long& d, unsigned long long a, unsigned long long b) {
    asm("fma.rn.f32x2 %0, %1, %2, %0;" : "+l"(d) : "l"(a), "l"(b));
}
__device__ __forceinline__ float2 upk2(unsigned long long v) {
    float lo, hi;
    asm("mov.b64 {%0, %1}, %2;" : "=f"(lo), "=f"(hi) : "l"(v));
    return make_float2(lo, hi);
}

// bf16 split helpers
__device__ __forceinline__ uint32_t bfpack(float x, float y) {
    __nv_bfloat162 h = __floats2bfloat162_rn(x, y);
    return *reinterpret_cast<uint32_t*>(&h);
}

// mma.sync m16n8k16 bf16 (standard PTX, no sm_103a features needed)
__device__ __forceinline__ void mma16816(float* d,
    uint32_t a0, uint32_t a1, uint32_t a2, uint32_t a3, uint32_t b0, uint32_t b1) {
    asm volatile(
        "mma.sync.aligned.m16n8k16.row.col.f32.bf16.bf16.f32 "
        "{%0,%1,%2,%3}, {%4,%5,%6,%7}, {%8,%9}, {%0,%1,%2,%3};"
        : "+f"(d[0]), "+f"(d[1]), "+f"(d[2]), "+f"(d[3])
        : "r"(a0), "r"(a1), "r"(a2), "r"(a3), "r"(b0), "r"(b1));
}

// ---------------- kernel 1: QKV = x @ qkv_weight.T + bias ----------------
__global__ __launch_bounds__(256) void qkv_kernel(
    const float* __restrict__ x, const float* __restrict__ W, const float* __restrict__ bias)
{
    __shared__ float xS[64 * 68];
    __shared__ float wS[64 * 68];
    const int part = blockIdx.y;
    const int row0 = blockIdx.x * 64;
    const int tid = threadIdx.x;

    #pragma unroll
    for (int p = 0; p < 4; p++) {
        int idx = tid + p * 256;
        int r = idx >> 4, c4 = idx & 15;
        float4 v = make_float4(0.f, 0.f, 0.f, 0.f);
        int gr = row0 + r;
        if (gr < N_NODES) v = ((const float4*)x)[gr * 16 + c4];
        *(float4*)&xS[r * 68 + c4 * 4] = v;
    }
    #pragma unroll
    for (int p = 0; p < 4; p++) {
        int idx = tid + p * 256;
        int c = idx >> 4, f = idx & 15;
        float4 v = ((const float4*)W)[(part * 64 + c) * 16 + f];
        wS[(f * 4 + 0) * 68 + c] = v.x;
        wS[(f * 4 + 1) * 68 + c] = v.y;
        wS[(f * 4 + 2) * 68 + c] = v.z;
        wS[(f * 4 + 3) * 68 + c] = v.w;
    }
    __syncthreads();

    const int tx = tid & 15, ty = tid >> 4;
    unsigned long long acc[4][2];
    #pragma unroll
    for (int i = 0; i < 4; i++) { acc[i][0] = 0ull; acc[i][1] = 0ull; }

    #pragma unroll 4
    for (int k = 0; k < 64; k++) {
        float4 b = *(float4*)&wS[k * 68 + tx * 4];
        unsigned long long b0 = pk2(b.x, b.y), b1 = pk2(b.z, b.w);
        #pragma unroll
        for (int i = 0; i < 4; i++) {
            float a = xS[(ty * 4 + i) * 68 + k];
            unsigned long long a2 = pk2(a, a);
            fma2(acc[i][0], a2, b0);
            fma2(acc[i][1], a2, b1);
        }
    }

    float* outBase = (part == 0) ? g_Q : (part == 1 ? g_K : g_V);
    float4 bv = ((const float4*)bias)[part * 16 + tx];
    #pragma unroll
    for (int i = 0; i < 4; i++) {
        int gr = row0 + ty * 4 + i;
        if (gr < N_NODES) {
            float2 p0 = upk2(acc[i][0]), p1 = upk2(acc[i][1]);
            float4 o = make_float4(p0.x + bv.x, p0.y + bv.y, p1.x + bv.z, p1.y + bv.w);
            *(float4*)&outBase[gr * 64 + tx * 4] = o;
        }
    }
}

// ---------------- CSR construction ----------------
__global__ void zero_kernel() {
    int i = blockIdx.x * blockDim.x + threadIdx.x;
    if (i < N_NODES) g_count[i] = 0;
}
__global__ void count_kernel(const int* __restrict__ eidx) {
    int e = blockIdx.x * blockDim.x + threadIdx.x;
    if (e < N_EDGES) atomicAdd(&g_count[eidx[e]], 1);
}
__global__ __launch_bounds__(256) void scanA_kernel() {
    __shared__ int ws[8];
    int t = threadIdx.x, i = blockIdx.x * 256 + t;
    int v = (i < N_NODES) ? g_count[i] : 0;
    #pragma unroll
    for (int o = 16; o > 0; o >>= 1) v += __shfl_down_sync(0xffffffffu, v, o);
    if ((t & 31) == 0) ws[t >> 5] = v;
    __syncthreads();
    if (t == 0) {
        int s = 0;
        #pragma unroll
        for (int w = 0; w < 8; w++) s += ws[w];
        g_bsum[blockIdx.x] = s;
    }
}
__global__ __launch_bounds__(256) void scanB_kernel() {
    __shared__ int ws[8];
    int t = threadIdx.x, lane = t & 31, w = t >> 5;
    int v = (t < SCAN_BLK) ? g_bsum[t] : 0;
    int x = v;
    #pragma unroll
    for (int o = 1; o < 32; o <<= 1) {
        int y = __shfl_up_sync(0xffffffffu, x, o);
        if (lane >= o) x += y;
    }
    if (lane == 31) ws[w] = x;
    __syncthreads();
    if (t == 0) {
        int run = 0;
        #pragma unroll
        for (int k = 0; k < 8; k++) { int tmp = ws[k]; ws[k] = run; run += tmp; }
    }
    __syncthreads();
    if (t < SCAN_BLK) g_boff[t] = x - v + ws[w];
    if (t == 0) g_off[N_NODES] = N_EDGES;
}
__global__ __launch_bounds__(256) void scanC_kernel() {
    __shared__ int ws[8];
    int t = threadIdx.x, lane = t & 31, w = t >> 5;
    int i = blockIdx.x * 256 + t;
    int v = (i < N_NODES) ? g_count[i] : 0;
    int x = v;
    #pragma unroll
    for (int o = 1; o < 32; o <<= 1) {
        int y = __shfl_up_sync(0xffffffffu, x, o);
        if (lane >= o) x += y;
    }
    if (lane == 31) ws[w] = x;
    __syncthreads();
    if (t == 0) {
        int run = 0;
        #pragma unroll
        for (int k = 0; k < 8; k++) { int tmp = ws[k]; ws[k] = run; run += tmp; }
    }
    __syncthreads();
    if (i < N_NODES) {
        int excl = x - v + ws[w] + g_boff[blockIdx.x];
        g_off[i] = excl;
        g_cursor[i] = excl;
    }
}
__global__ void scatter_kernel(const int* __restrict__ eidx) {
    int e = blockIdx.x * blockDim.x + threadIdx.x;
    if (e < N_EDGES) {
        int dst = eidx[e];
        int pos = atomicAdd(&g_cursor[dst], 1);
        g_order[pos] = e;
    }
}

// ---------------- kernel 2: split-bf16 HMMA edge GEMM + fused epilogue ----------------
// D[128 edges, 128 cols] = cf_tile @ EW^T  via mma.sync m16n8k16 bf16,
// 3 split passes (AhBh + AhBl + AlBh) for fp32-grade accuracy.
// 256 threads = 8 warps; warp w owns edges w*16..w*16+15, all 128 cols.
// A/B bf16 smem stride 72 elems (144B): frag LDS conflict-free.
// D written to smem (stride 136 floats, conflict-free v2 stores) overlaying
// A/B, then R6's epilogue (tx4/tg mapping) runs from Ds.
#define SM_AHI 0
#define SM_ALO 18432
#define SM_BHI 36864
#define SM_BLO 55296
#define SM_MISC 73728                     // sDst 512 | sSrc 512 | awS 256 | ebS 512
#define SMEM_EDGE (SM_MISC + 512 + 512 + 256 + 512)
#define ASTRIDE 144                       // bytes per bf16 row (72 elems)
#define DSTRIDE 136                       // floats per D row

__global__ __launch_bounds__(256) void edge_kernel(
    const float* __restrict__ cf, const float* __restrict__ EW,
    const float* __restrict__ Ebias, const int* __restrict__ eidx,
    const float* __restrict__ Aw, float* __restrict__ conn_out)
{
    extern __shared__ char smem[];
    const int tid = threadIdx.x;
    const int e0 = blockIdx.x * 128;

    int* sDst = (int*)(smem + SM_MISC);
    int* sSrc = (int*)(smem + SM_MISC + 512);
    float* awS = (float*)(smem + SM_MISC + 1024);
    float* ebS = (float*)(smem + SM_MISC + 1280);

    // ---- loaders: convert fp32 -> (hi, lo) bf16 pairs ----
    {
        const int r = tid >> 1;              // row 0..127
        const int cb = (tid & 1) * 32;       // col base 0 or 32
        const float4* arow = (const float4*)(cf + (size_t)(e0 + r) * 64 + cb);
        const float4* brow = (const float4*)(EW + (size_t)r * 64 + cb);
        #pragma unroll
        for (int q = 0; q < 8; q++) {
            float4 v = arow[q];
            __nv_bfloat16 hx = __float2bfloat16(v.x), hy = __float2bfloat16(v.y);
            __nv_bfloat16 hz = __float2bfloat16(v.z), hw = __float2bfloat16(v.w);
            uint32_t h0 = bfpack(__bfloat162float(hx), __bfloat162float(hy));
            uint32_t h1 = bfpack(__bfloat162float(hz), __bfloat162float(hw));
            uint32_t l0 = bfpack(v.x - __bfloat162float(hx), v.y - __bfloat162float(hy));
            uint32_t l1 = bfpack(v.z - __bfloat162float(hz), v.w - __bfloat162float(hw));
            uint32_t off = r * ASTRIDE + (cb + q * 4) * 2;
            *(uint32_t*)(smem + SM_AHI + off) = h0;
            *(uint32_t*)(smem + SM_AHI + off + 4) = h1;
            *(uint32_t*)(smem + SM_ALO + off) = l0;
            *(uint32_t*)(smem + SM_ALO + off + 4) = l1;

            float4 u = brow[q];
            hx = __float2bfloat16(u.x); hy = __float2bfloat16(u.y);
            hz = __float2bfloat16(u.z); hw = __float2bfloat16(u.w);
            h0 = bfpack(__bfloat162float(hx), __bfloat162float(hy));
            h1 = bfpack(__bfloat162float(hz), __bfloat162float(hw));
            l0 = bfpack(u.x - __bfloat162float(hx), u.y - __bfloat162float(hy));
            l1 = bfpack(u.z - __bfloat162float(hz), u.w - __bfloat162float(hw));
            *(uint32_t*)(smem + SM_BHI + off) = h0;
            *(uint32_t*)(smem + SM_BHI + off + 4) = h1;
            *(uint32_t*)(smem + SM_BLO + off) = l0;
            *(uint32_t*)(smem + SM_BLO + off + 4) = l1;
        }
    }
    if (tid < 128) {
        sDst[tid] = eidx[e0 + tid];
        sSrc[tid] = eidx[N_EDGES + e0 + tid];
    }
    if (tid >= 128 && tid < 192) awS[tid - 128] = Aw[tid - 128];
    if (tid >= 64 && tid < 192) ebS[tid - 64] = Ebias[tid - 64];
    __syncthreads();

    // ---- MMA mainloop ----
    const int wid = tid >> 5, lane = tid & 31;
    const int gid = lane >> 2, tig = lane & 3;
    const int m0off = (wid * 16 + gid) * ASTRIDE;

    float d[16][4];
    #pragma unroll
    for (int nt = 0; nt < 16; nt++)
        #pragma unroll
        for (int p = 0; p < 4; p++) d[nt][p] = 0.f;

    #pragma unroll 1
    for (int ks = 0; ks < 4; ks++) {
        const uint32_t k0b = (ks * 16 + tig * 2) * 2;   // byte offset of k0
        uint32_t ah0 = *(const uint32_t*)(smem + SM_AHI + m0off + k0b);
        uint32_t ah1 = *(const uint32_t*)(smem + SM_AHI + m0off + 8 * ASTRIDE + k0b);
        uint32_t ah2 = *(const uint32_t*)(smem + SM_AHI + m0off + k0b + 16);
        uint32_t ah3 = *(const uint32_t*)(smem + SM_AHI + m0off + 8 * ASTRIDE + k0b + 16);
        uint32_t al0 = *(const uint32_t*)(smem + SM_ALO + m0off + k0b);
        uint32_t al1 = *(const uint32_t*)(smem + SM_ALO + m0off + 8 * ASTRIDE + k0b);
        uint32_t al2 = *(const uint32_t*)(smem + SM_ALO + m0off + k0b + 16);
        uint32_t al3 = *(const uint32_t*)(smem + SM_ALO + m0off + 8 * ASTRIDE + k0b + 16);
        #pragma unroll
        for (int nt = 0; nt < 16; nt++) {
            uint32_t noff = (nt * 8 + gid) * ASTRIDE + k0b;
            uint32_t bh0 = *(const uint32_t*)(smem + SM_BHI + noff);
            uint32_t bh1 = *(const uint32_t*)(smem + SM_BHI + noff + 16);
            uint32_t bl0 = *(const uint32_t*)(smem + SM_BLO + noff);
            uint32_t bl1 = *(const uint32_t*)(smem + SM_BLO + noff + 16);
            mma16816(d[nt], ah0, ah1, ah2, ah3, bh0, bh1);
            mma16816(d[nt], ah0, ah1, ah2, ah3, bl0, bl1);
            mma16816(d[nt], al0, al1, al2, al3, bh0, bh1);
        }
    }
    __syncthreads();   // everyone done reading A/B before D overlays

    // ---- write D to smem (overlaying A/B region) ----
    float* Ds = (float*)smem;
    {
        const int m0 = wid * 16 + gid;
        #pragma unroll
        for (int nt = 0; nt < 16; nt++) {
            int col = nt * 8 + tig * 2;
            *(float2*)&Ds[m0 * DSTRIDE + col] = make_float2(d[nt][0], d[nt][1]);
            *(float2*)&Ds[(m0 + 8) * DSTRIDE + col] = make_float2(d[nt][2], d[nt][3]);
        }
    }
    __syncthreads();

    // ---- R6 epilogue (tx4 = col chunk, tg = edge group of 8) ----
    const int tx4 = tid & 15;
    const int tg = tid >> 4;
    const int h = tx4 >> 1;
    const int dimb = (tx4 & 1) * 4;

    const float ebw0 = ebS[tx4 * 4 + 0], ebw1 = ebS[tx4 * 4 + 1];
    const float ebw2 = ebS[tx4 * 4 + 2], ebw3 = ebS[tx4 * 4 + 3];
    const float ebb0 = ebS[64 + tx4 * 4 + 0], ebb1 = ebS[64 + tx4 * 4 + 1];
    const float ebb2 = ebS[64 + tx4 * 4 + 2], ebb3 = ebS[64 + tx4 * 4 + 3];
    const float aw0 = awS[(dimb + 0) * 8 + h], aw1 = awS[(dimb + 1) * 8 + h];
    const float aw2 = awS[(dimb + 2) * 8 + h], aw3 = awS[(dimb + 3) * 8 + h];

    #pragma unroll
    for (int j = 0; j < 8; j++) {
        int el = tg * 8 + j;
        int e = e0 + el;
        int dn = sDst[el], sn = sSrc[el];
        float4 q = ((const float4*)g_Q)[dn * 16 + tx4];
        float4 kk = ((const float4*)g_K)[sn * 16 + tx4];
        float qk[4] = {q.x + kk.x, q.y + kk.y, q.z + kk.z, q.w + kk.w};
        float4 ewv = *(float4*)&Ds[el * DSTRIDE + tx4 * 4];
        float4 ebv = *(float4*)&Ds[el * DSTRIDE + 64 + tx4 * 4];
        float ew[4] = {ewv.x, ewv.y, ewv.z, ewv.w};
        float eb[4] = {ebv.x, ebv.y, ebv.z, ebv.w};
        float ebw[4] = {ebw0, ebw1, ebw2, ebw3};
        float ebb[4] = {ebb0, ebb1, ebb2, ebb3};
        float conn[4];
        #pragma unroll
        for (int m = 0; m < 4; m++) {
            float c1 = qk[m] * (ew[m] + ebw[m]);
            float c2 = copysignf(sqrtf(fabsf(c1)), c1);
            conn[m] = fmaxf(c2 + (eb[m] + ebb[m]), 0.f);
        }
        *(float4*)&conn_out[(long long)e * 64 + tx4 * 4] =
            make_float4(conn[0], conn[1], conn[2], conn[3]);
        float scp = conn[0] * aw0 + conn[1] * aw1 + conn[2] * aw2 + conn[3] * aw3;
        float sc = scp + __shfl_xor_sync(0xffffffffu, scp, 1);
        sc = fminf(fmaxf(sc, -CLAMP_V), CLAMP_V);
        if ((tx4 & 1) == 0) g_w[e * 8 + h] = expf(sc);
    }
}

// ---------------- kernel 3: per-node aggregation (warp per node) ----------------
__global__ __launch_bounds__(256) void node_kernel(
    const float* __restrict__ conn_out, const int* __restrict__ eidx,
    const float* __restrict__ Bw, float* __restrict__ No)
{
    __shared__ float bwS[512];
    int tid = threadIdx.x;
    bwS[tid] = Bw[tid];
    bwS[tid + 256] = Bw[tid + 256];
    __syncthreads();

    const int warp = tid >> 5, lane = tid & 31;
    const int n = blockIdx.x * 8 + warp;
    const int j0 = g_off[n], j1 = g_off[n + 1];
    const int h0 = lane >> 3, h1 = h0 + 4, c = lane & 7, base = lane & 24;
    const int* srcArr = eidx + N_EDGES;

    float s0 = 0.f, s1 = 0.f, agg0 = 0.f, agg1 = 0.f, rv0 = 0.f, rv1 = 0.f;
    int e = (j0 < j1) ? g_order[j0] : 0;
    for (int j = j0; j < j1; j++) {
        int e_next = (j + 1 < j1) ? g_order[j + 1] : 0;
        int src = srcArr[e];
        float w0 = g_w[e * 8 + h0];
        float w1 = g_w[e * 8 + h1];
        float c0 = conn_out[(long long)e * 64 + lane];
        float c1 = conn_out[(long long)e * 64 + 32 + lane];
        float v0 = g_V[src * 64 + lane];
        float v1 = g_V[src * 64 + 32 + lane];
        s0 += w0; s1 += w1;
        agg0 = fmaf(w0, v0, agg0); rv0 = fmaf(w0, c0, rv0);
        agg1 = fmaf(w1, v1, agg1); rv1 = fmaf(w1, c1, rv1);
        e = e_next;
    }
    float inv0 = (s0 > 0.f) ? 1.f / s0 : 0.f;
    float inv1 = (s1 > 0.f) ? 1.f / s1 : 0.f;
    float rn0 = rv0 * inv0, rn1 = rv1 * inv1;
    float o0 = 0.f, o1 = 0.f;
    #pragma unroll
    for (int dd = 0; dd < 8; dd++) {
        float r0 = __shfl_sync(0xffffffffu, rn0, base + dd);
        float r1 = __shfl_sync(0xffffffffu, rn1, base + dd);
        o0 = fmaf(r0, bwS[dd * 64 + h0 * 8 + c], o0);
        o1 = fmaf(r1, bwS[dd * 64 + h1 * 8 + c], o1);
    }
    No[n * 64 + lane] = fmaf(agg0, inv0, o0);
    No[n * 64 + 32 + lane] = fmaf(agg1, inv1, o1);
}

// ---------------- launch ----------------
extern "C" void kernel_launch(void* const* d_in, const int* in_sizes, int n_in,
                              void* d_out, int out_size)
{
    const float* x       = (const float*)d_in[0];
    const float* cf      = (const float*)d_in[1];
    const int*   eidx    = (const int*)d_in[2];
    const float* qkvW    = (const float*)d_in[3];
    const float* qkvB    = (const float*)d_in[4];
    const float* EW      = (const float*)d_in[5];
    const float* EB      = (const float*)d_in[6];
    const float* Aw      = (const float*)d_in[7];
    const float* Bw      = (const float*)d_in[8];

    float* No = (float*)d_out;
    float* conn_out = No + (size_t)N_NODES * 64;

    cudaFuncSetAttribute(edge_kernel, cudaFuncAttributeMaxDynamicSharedMemorySize, SMEM_EDGE);

    // ncu (-s 5 -c 1) profiles OUR 4th launch; keep edge_kernel there.
    zero_kernel<<<(N_NODES + 255) / 256, 256>>>();                         // 1
    qkv_kernel<<<dim3((N_NODES + 63) / 64, 3), 256>>>(x, qkvW, qkvB);      // 2
    count_kernel<<<(N_EDGES + 255) / 256, 256>>>(eidx);                    // 3
    edge_kernel<<<N_EDGES / 128, 256, SMEM_EDGE>>>(cf, EW, EB, eidx, Aw, conn_out); // 4 <- profiled
    scanA_kernel<<<SCAN_BLK, 256>>>();                                     // 5
    scanB_kernel<<<1, 256>>>();                                            // 6
    scanC_kernel<<<SCAN_BLK, 256>>>();                                     // 7
    scatter_kernel<<<(N_EDGES + 255) / 256, 256>>>(eidx);                  // 8
    node_kernel<<<N_NODES / 8, 256>>>(conn_out, eidx, Bw, No);             // 9
}

// round 9
// speedup vs baseline: 1.4546x; 1.0433x over previous
#include <cuda_runtime.h>
#include <cuda_bf16.h>
#include <cstdint>

#define N_NODES 50000
#define N_EDGES 800000
#define HEADS 8
#define ADIM 8
#define HD 64            // HEADS*ADIM
#define CLAMP_V 5.0f
#define SCAN_BLK 196     // ceil(50000/256)

// ---------------- scratch (device globals: allocation-free rule) ----------------
__device__ __align__(16) float g_Q[N_NODES * HD];
__device__ __align__(16) float g_K[N_NODES * HD];
__device__ __align__(16) float g_V[N_NODES * HD];
__device__ __align__(16) float g_w[N_EDGES * HEADS];   // exp(clamped score)
__device__ int g_count[N_NODES];
__device__ int g_off[N_NODES + 1];
__device__ int g_cursor[N_NODES];
__device__ int g_order[N_EDGES];
__device__ int g_bsum[SCAN_BLK];
__device__ int g_boff[SCAN_BLK];
// precomputed EW hi/lo in frag layout (row stride 36 words = 144B)
__device__ __align__(16) unsigned g_Bhi[128 * 36];
__device__ __align__(16) unsigned g_Blo[128 * 36];

// ---------------- f32x2 packed FMA helpers (qkv kernel) ----------------
__device__ __forceinline__ unsigned long long pk2(float lo, float hi) {
    unsigned long long r;
    asm("mov.b64 %0, {%1, %2};" : "=l"(r) : "f"(lo), "f"(hi));
    return r;
}
__device__ __forceinline__ void fma2(unsigned long long& d, unsigned long long a, unsigned long long b) {
    asm("fma.rn.f32x2 %0, %1, %2, %0;" : "+l"(d) : "l"(a), "l"(b));
}
__device__ __forceinline__ float2 upk2(unsigned long long v) {
    float lo, hi;
    asm("mov.b64 {%0, %1}, %2;" : "=f"(lo), "=f"(hi) : "l"(v));
    return make_float2(lo, hi);
}

// bf16 split helpers
__device__ __forceinline__ uint32_t bfpack(float x, float y) {
    __nv_bfloat162 h = __floats2bfloat162_rn(x, y);
    return *reinterpret_cast<uint32_t*>(&h);
}

// mma.sync m16n8k16 bf16 (standard PTX)
__device__ __forceinline__ void mma16816(float* d,
    uint32_t a0, uint32_t a1, uint32_t a2, uint32_t a3, uint32_t b0, uint32_t b1) {
    asm volatile(
        "mma.sync.aligned.m16n8k16.row.col.f32.bf16.bf16.f32 "
        "{%0,%1,%2,%3}, {%4,%5,%6,%7}, {%8,%9}, {%0,%1,%2,%3};"
        : "+f"(d[0]), "+f"(d[1]), "+f"(d[2]), "+f"(d[3])
        : "r"(a0), "r"(a1), "r"(a2), "r"(a3), "r"(b0), "r"(b1));
}

// ---------------- kernel 1: QKV = x @ qkv_weight.T + bias ----------------
__global__ __launch_bounds__(256) void qkv_kernel(
    const float* __restrict__ x, const float* __restrict__ W, const float* __restrict__ bias)
{
    __shared__ float xS[64 * 68];
    __shared__ float wS[64 * 68];
    const int part = blockIdx.y;
    const int row0 = blockIdx.x * 64;
    const int tid = threadIdx.x;

    #pragma unroll
    for (int p = 0; p < 4; p++) {
        int idx = tid + p * 256;
        int r = idx >> 4, c4 = idx & 15;
        float4 v = make_float4(0.f, 0.f, 0.f, 0.f);
        int gr = row0 + r;
        if (gr < N_NODES) v = ((const float4*)x)[gr * 16 + c4];
        *(float4*)&xS[r * 68 + c4 * 4] = v;
    }
    #pragma unroll
    for (int p = 0; p < 4; p++) {
        int idx = tid + p * 256;
        int c = idx >> 4, f = idx & 15;
        float4 v = ((const float4*)W)[(part * 64 + c) * 16 + f];
        wS[(f * 4 + 0) * 68 + c] = v.x;
        wS[(f * 4 + 1) * 68 + c] = v.y;
        wS[(f * 4 + 2) * 68 + c] = v.z;
        wS[(f * 4 + 3) * 68 + c] = v.w;
    }
    __syncthreads();

    const int tx = tid & 15, ty = tid >> 4;
    unsigned long long acc[4][2];
    #pragma unroll
    for (int i = 0; i < 4; i++) { acc[i][0] = 0ull; acc[i][1] = 0ull; }

    #pragma unroll 4
    for (int k = 0; k < 64; k++) {
        float4 b = *(float4*)&wS[k * 68 + tx * 4];
        unsigned long long b0 = pk2(b.x, b.y), b1 = pk2(b.z, b.w);
        #pragma unroll
        for (int i = 0; i < 4; i++) {
            float a = xS[(ty * 4 + i) * 68 + k];
            unsigned long long a2 = pk2(a, a);
            fma2(acc[i][0], a2, b0);
            fma2(acc[i][1], a2, b1);
        }
    }

    float* outBase = (part == 0) ? g_Q : (part == 1 ? g_K : g_V);
    float4 bv = ((const float4*)bias)[part * 16 + tx];
    #pragma unroll
    for (int i = 0; i < 4; i++) {
        int gr = row0 + ty * 4 + i;
        if (gr < N_NODES) {
            float2 p0 = upk2(acc[i][0]), p1 = upk2(acc[i][1]);
            float4 o = make_float4(p0.x + bv.x, p0.y + bv.y, p1.x + bv.z, p1.y + bv.w);
            *(float4*)&outBase[gr * 64 + tx * 4] = o;
        }
    }
}

// ---------------- prep: convert EW -> hi/lo bf16 frag layout (once) ----------------
__global__ __launch_bounds__(256) void prep_kernel(const float* __restrict__ EW) {
    const int tid = threadIdx.x;
    const int r = tid >> 1;
    const int cb = (tid & 1) * 32;
    const float4* brow = (const float4*)(EW + (size_t)r * 64 + cb);
    uint2* bh = (uint2*)g_Bhi;
    uint2* bl = (uint2*)g_Blo;
    #pragma unroll
    for (int q = 0; q < 8; q++) {
        float4 u = brow[q];
        __nv_bfloat16 hx = __float2bfloat16(u.x), hy = __float2bfloat16(u.y);
        __nv_bfloat16 hz = __float2bfloat16(u.z), hw = __float2bfloat16(u.w);
        uint32_t h0 = bfpack(__bfloat162float(hx), __bfloat162float(hy));
        uint32_t h1 = bfpack(__bfloat162float(hz), __bfloat162float(hw));
        uint32_t l0 = bfpack(u.x - __bfloat162float(hx), u.y - __bfloat162float(hy));
        uint32_t l1 = bfpack(u.z - __bfloat162float(hz), u.w - __bfloat162float(hw));
        int p = r * 18 + cb / 4 + q;       // uint2 index
        bh[p] = make_uint2(h0, h1);
        bl[p] = make_uint2(l0, l1);
    }
}

// ---------------- CSR construction ----------------
__global__ void zero_kernel() {
    int i = blockIdx.x * blockDim.x + threadIdx.x;
    if (i < N_NODES) g_count[i] = 0;
}
__global__ __launch_bounds__(256) void scanA_kernel() {
    __shared__ int ws[8];
    int t = threadIdx.x, i = blockIdx.x * 256 + t;
    int v = (i < N_NODES) ? g_count[i] : 0;
    #pragma unroll
    for (int o = 16; o > 0; o >>= 1) v += __shfl_down_sync(0xffffffffu, v, o);
    if ((t & 31) == 0) ws[t >> 5] = v;
    __syncthreads();
    if (t == 0) {
        int s = 0;
        #pragma unroll
        for (int w = 0; w < 8; w++) s += ws[w];
        g_bsum[blockIdx.x] = s;
    }
}
__global__ __launch_bounds__(256) void scanB_kernel() {
    __shared__ int ws[8];
    int t = threadIdx.x, lane = t & 31, w = t >> 5;
    int v = (t < SCAN_BLK) ? g_bsum[t] : 0;
    int x = v;
    #pragma unroll
    for (int o = 1; o < 32; o <<= 1) {
        int y = __shfl_up_sync(0xffffffffu, x, o);
        if (lane >= o) x += y;
    }
    if (lane == 31) ws[w] = x;
    __syncthreads();
    if (t == 0) {
        int run = 0;
        #pragma unroll
        for (int k = 0; k < 8; k++) { int tmp = ws[k]; ws[k] = run; run += tmp; }
    }
    __syncthreads();
    if (t < SCAN_BLK) g_boff[t] = x - v + ws[w];
    if (t == 0) g_off[N_NODES] = N_EDGES;
}
__global__ __launch_bounds__(256) void scanC_kernel() {
    __shared__ int ws[8];
    int t = threadIdx.x, lane = t & 31, w = t >> 5;
    int i = blockIdx.x * 256 + t;
    int v = (i < N_NODES) ? g_count[i] : 0;
    int x = v;
    #pragma unroll
    for (int o = 1; o < 32; o <<= 1) {
        int y = __shfl_up_sync(0xffffffffu, x, o);
        if (lane >= o) x += y;
    }
    if (lane == 31) ws[w] = x;
    __syncthreads();
    if (t == 0) {
        int run = 0;
        #pragma unroll
        for (int k = 0; k < 8; k++) { int tmp = ws[k]; ws[k] = run; run += tmp; }
    }
    __syncthreads();
    if (i < N_NODES) {
        int excl = x - v + ws[w] + g_boff[blockIdx.x];
        g_off[i] = excl;
        g_cursor[i] = excl;
    }
}
__global__ void scatter_kernel(const int* __restrict__ eidx) {
    int e = blockIdx.x * blockDim.x + threadIdx.x;
    if (e < N_EDGES) {
        int dst = eidx[e];
        int pos = atomicAdd(&g_cursor[dst], 1);
        g_order[pos] = e;
    }
}

// ---------------- kernel 2: split-bf16 HMMA edge GEMM + in-register epilogue ----
// D[128 edges, 128 cols] = cf_tile @ EW^T via mma.sync m16n8k16 bf16,
// 3 split passes. Warp w: edges w*16..+15, all 128 cols.
// Epilogue runs from D registers directly (no smem roundtrip):
//   thread (gid,tig) holds rows gid/gid+8, cols nt*8+tig*2+{0,1};
//   Ew part = d[nt], Eb part = d[nt+8]; head h = nt; score reduced over
//   the 4 tig lanes with shfl_xor(1), shfl_xor(2).
// Also fuses the per-edge g_count atomicAdd (count_kernel removed).
#define SM_AHI 0
#define SM_ALO 18432
#define SM_BHI 36864
#define SM_BLO 55296
#define SM_MISC 73728                     // sDst 512 | sSrc 512 | awS 256 | ebS 512
#define SMEM_EDGE (SM_MISC + 512 + 512 + 256 + 512)
#define ASTRIDE 144                       // bytes per bf16 row (72 elems)

__global__ __launch_bounds__(256) void edge_kernel(
    const float* __restrict__ cf,
    const float* __restrict__ Ebias, const int* __restrict__ eidx,
    const float* __restrict__ Aw, float* __restrict__ conn_out)
{
    extern __shared__ char smem[];
    const int tid = threadIdx.x;
    const int e0 = blockIdx.x * 128;

    int* sDst = (int*)(smem + SM_MISC);
    int* sSrc = (int*)(smem + SM_MISC + 512);
    float* awS = (float*)(smem + SM_MISC + 1024);
    float* ebS = (float*)(smem + SM_MISC + 1280);

    // ---- A loader: convert fp32 -> (hi, lo) bf16 pairs ----
    {
        const int r = tid >> 1;
        const int cb = (tid & 1) * 32;
        const float4* arow = (const float4*)(cf + (size_t)(e0 + r) * 64 + cb);
        #pragma unroll
        for (int q = 0; q < 8; q++) {
            float4 v = arow[q];
            __nv_bfloat16 hx = __float2bfloat16(v.x), hy = __float2bfloat16(v.y);
            __nv_bfloat16 hz = __float2bfloat16(v.z), hw = __float2bfloat16(v.w);
            uint32_t h0 = bfpack(__bfloat162float(hx), __bfloat162float(hy));
            uint32_t h1 = bfpack(__bfloat162float(hz), __bfloat162float(hw));
            uint32_t l0 = bfpack(v.x - __bfloat162float(hx), v.y - __bfloat162float(hy));
            uint32_t l1 = bfpack(v.z - __bfloat162float(hz), v.w - __bfloat162float(hw));
            uint32_t off = r * ASTRIDE + (cb + q * 4) * 2;
            *(uint2*)(smem + SM_AHI + off) = make_uint2(h0, h1);
            *(uint2*)(smem + SM_ALO + off) = make_uint2(l0, l1);
        }
    }
    // ---- B loader: plain copy of preconverted frag-layout tiles ----
    {
        const uint4* bh = (const uint4*)g_Bhi;
        const uint4* bl = (const uint4*)g_Blo;
        uint4* dh = (uint4*)(smem + SM_BHI);
        uint4* dl = (uint4*)(smem + SM_BLO);
        #pragma unroll
        for (int i = tid; i < 1152; i += 256) { dh[i] = bh[i]; dl[i] = bl[i]; }
    }
    if (tid < 128) {
        int dv = eidx[e0 + tid];
        int sv = eidx[N_EDGES + e0 + tid];
        sDst[tid] = dv;
        sSrc[tid] = sv;
        atomicAdd(&g_count[dv], 1);       // fused count_kernel
    }
    if (tid >= 128 && tid < 192) awS[tid - 128] = Aw[tid - 128];
    if (tid >= 64 && tid < 192) ebS[tid - 64] = Ebias[tid - 64];
    __syncthreads();

    // ---- MMA mainloop ----
    const int wid = tid >> 5, lane = tid & 31;
    const int gid = lane >> 2, tig = lane & 3;
    const int m0off = (wid * 16 + gid) * ASTRIDE;

    float d[16][4];
    #pragma unroll
    for (int nt = 0; nt < 16; nt++)
        #pragma unroll
        for (int p = 0; p < 4; p++) d[nt][p] = 0.f;

    #pragma unroll 1
    for (int ks = 0; ks < 4; ks++) {
        const uint32_t k0b = (ks * 16 + tig * 2) * 2;
        uint32_t ah0 = *(const uint32_t*)(smem + SM_AHI + m0off + k0b);
        uint32_t ah1 = *(const uint32_t*)(smem + SM_AHI + m0off + 8 * ASTRIDE + k0b);
        uint32_t ah2 = *(const uint32_t*)(smem + SM_AHI + m0off + k0b + 16);
        uint32_t ah3 = *(const uint32_t*)(smem + SM_AHI + m0off + 8 * ASTRIDE + k0b + 16);
        uint32_t al0 = *(const uint32_t*)(smem + SM_ALO + m0off + k0b);
        uint32_t al1 = *(const uint32_t*)(smem + SM_ALO + m0off + 8 * ASTRIDE + k0b);
        uint32_t al2 = *(const uint32_t*)(smem + SM_ALO + m0off + k0b + 16);
        uint32_t al3 = *(const uint32_t*)(smem + SM_ALO + m0off + 8 * ASTRIDE + k0b + 16);
        #pragma unroll
        for (int nt = 0; nt < 16; nt++) {
            uint32_t noff = (nt * 8 + gid) * ASTRIDE + k0b;
            uint32_t bh0 = *(const uint32_t*)(smem + SM_BHI + noff);
            uint32_t bh1 = *(const uint32_t*)(smem + SM_BHI + noff + 16);
            uint32_t bl0 = *(const uint32_t*)(smem + SM_BLO + noff);
            uint32_t bl1 = *(const uint32_t*)(smem + SM_BLO + noff + 16);
            mma16816(d[nt], ah0, ah1, ah2, ah3, bh0, bh1);
            mma16816(d[nt], ah0, ah1, ah2, ah3, bl0, bl1);
            mma16816(d[nt], al0, al1, al2, al3, bh0, bh1);
        }
    }

    // ---- in-register epilogue (no syncthreads needed: only regs + read-only smem) ----
    const int c0 = tig * 2;                // col within head octet
    const float awA = awS[c0 * 8 + 0];     // placeholder to keep indices simple
    (void)awA;
    #pragma unroll
    for (int er = 0; er < 2; er++) {
        const int el = wid * 16 + gid + er * 8;
        const int e = e0 + el;
        const int dn = sDst[el], sn = sSrc[el];
        float wv[8];
        #pragma unroll
        for (int nt = 0; nt < 8; nt++) {
            const int cc = nt * 8 + c0;
            float2 q2 = *(const float2*)&g_Q[(size_t)dn * 64 + cc];
            float2 k2 = *(const float2*)&g_K[(size_t)sn * 64 + cc];
            float qk0 = q2.x + k2.x, qk1 = q2.y + k2.y;
            float ew0 = d[nt][er * 2 + 0] + ebS[cc];
            float ew1 = d[nt][er * 2 + 1] + ebS[cc + 1];
            float eb0 = d[nt + 8][er * 2 + 0] + ebS[64 + cc];
            float eb1 = d[nt + 8][er * 2 + 1] + ebS[64 + cc + 1];
            float c1a = qk0 * ew0;
            float c1b = qk1 * ew1;
            float conn0 = fmaxf(copysignf(sqrtf(fabsf(c1a)), c1a) + eb0, 0.f);
            float conn1 = fmaxf(copysignf(sqrtf(fabsf(c1b)), c1b) + eb1, 0.f);
            *(float2*)&conn_out[(long long)e * 64 + cc] = make_float2(conn0, conn1);
            float sp = conn0 * awS[c0 * 8 + nt] + conn1 * awS[(c0 + 1) * 8 + nt];
            sp += __shfl_xor_sync(0xffffffffu, sp, 1);
            sp += __shfl_xor_sync(0xffffffffu, sp, 2);
            wv[nt] = expf(fminf(fmaxf(sp, -CLAMP_V), CLAMP_V));
        }
        if (tig == 0) {
            ((float4*)g_w)[e * 2] = make_float4(wv[0], wv[1], wv[2], wv[3]);
            ((float4*)g_w)[e * 2 + 1] = make_float4(wv[4], wv[5], wv[6], wv[7]);
        }
    }
}

// ---------------- kernel 3: per-node aggregation (warp per node) ----------------
__global__ __launch_bounds__(256) void node_kernel(
    const float* __restrict__ conn_out, const int* __restrict__ eidx,
    const float* __restrict__ Bw, float* __restrict__ No)
{
    __shared__ float bwS[512];
    int tid = threadIdx.x;
    bwS[tid] = Bw[tid];
    bwS[tid + 256] = Bw[tid + 256];
    __syncthreads();

    const int warp = tid >> 5, lane = tid & 31;
    const int n = blockIdx.x * 8 + warp;
    const int j0 = g_off[n], j1 = g_off[n + 1];
    const int h0 = lane >> 3, h1 = h0 + 4, c = lane & 7, base = lane & 24;
    const int* srcArr = eidx + N_EDGES;

    float s0 = 0.f, s1 = 0.f, agg0 = 0.f, agg1 = 0.f, rv0 = 0.f, rv1 = 0.f;
    int e = (j0 < j1) ? g_order[j0] : 0;
    for (int j = j0; j < j1; j++) {
        int e_next = (j + 1 < j1) ? g_order[j + 1] : 0;
        int src = srcArr[e];
        float w0 = g_w[e * 8 + h0];
        float w1 = g_w[e * 8 + h1];
        float c0 = conn_out[(long long)e * 64 + lane];
        float c1 = conn_out[(long long)e * 64 + 32 + lane];
        float v0 = g_V[src * 64 + lane];
        float v1 = g_V[src * 64 + 32 + lane];
        s0 += w0; s1 += w1;
        agg0 = fmaf(w0, v0, agg0); rv0 = fmaf(w0, c0, rv0);
        agg1 = fmaf(w1, v1, agg1); rv1 = fmaf(w1, c1, rv1);
        e = e_next;
    }
    float inv0 = (s0 > 0.f) ? 1.f / s0 : 0.f;
    float inv1 = (s1 > 0.f) ? 1.f / s1 : 0.f;
    float rn0 = rv0 * inv0, rn1 = rv1 * inv1;
    float o0 = 0.f, o1 = 0.f;
    #pragma unroll
    for (int dd = 0; dd < 8; dd++) {
        float r0 = __shfl_sync(0xffffffffu, rn0, base + dd);
        float r1 = __shfl_sync(0xffffffffu, rn1, base + dd);
        o0 = fmaf(r0, bwS[dd * 64 + h0 * 8 + c], o0);
        o1 = fmaf(r1, bwS[dd * 64 + h1 * 8 + c], o1);
    }
    No[n * 64 + lane] = fmaf(agg0, inv0, o0);
    No[n * 64 + 32 + lane] = fmaf(agg1, inv1, o1);
}

// ---------------- launch ----------------
extern "C" void kernel_launch(void* const* d_in, const int* in_sizes, int n_in,
                              void* d_out, int out_size)
{
    const float* x       = (const float*)d_in[0];
    const float* cf      = (const float*)d_in[1];
    const int*   eidx    = (const int*)d_in[2];
    const float* qkvW    = (const float*)d_in[3];
    const float* qkvB    = (const float*)d_in[4];
    const float* EW      = (const float*)d_in[5];
    const float* EB      = (const float*)d_in[6];
    const float* Aw      = (const float*)d_in[7];
    const float* Bw      = (const float*)d_in[8];

    float* No = (float*)d_out;
    float* conn_out = No + (size_t)N_NODES * 64;

    cudaFuncSetAttribute(edge_kernel, cudaFuncAttributeMaxDynamicSharedMemorySize, SMEM_EDGE);

    // ncu (-s 5 -c 1) profiles OUR 4th launch -> edge_kernel.
    zero_kernel<<<(N_NODES + 255) / 256, 256>>>();                         // 1
    qkv_kernel<<<dim3((N_NODES + 63) / 64, 3), 256>>>(x, qkvW, qkvB);      // 2
    prep_kernel<<<1, 256>>>(EW);                                           // 3
    edge_kernel<<<N_EDGES / 128, 256, SMEM_EDGE>>>(cf, EB, eidx, Aw, conn_out); // 4 <- profiled
    scanA_kernel<<<SCAN_BLK, 256>>>();                                     // 5
    scanB_kernel<<<1, 256>>>();                                            // 6
    scanC_kernel<<<SCAN_BLK, 256>>>();                                     // 7
    scatter_kernel<<<(N_EDGES + 255) / 256, 256>>>(eidx);                  // 8
    node_kernel<<<N_NODES / 8, 256>>>(conn_out, eidx, Bw, No);             // 9
}

// round 10
// speedup vs baseline: 1.4720x; 1.0120x over previous
#include <cuda_runtime.h>
#include <cuda_bf16.h>
#include <cstdint>

#define N_NODES 50000
#define N_EDGES 800000
#define HEADS 8
#define ADIM 8
#define HD 64            // HEADS*ADIM
#define CLAMP_V 5.0f
#define SCAN_BLK 196     // ceil(50000/256)

// ---------------- scratch (device globals: allocation-free rule) ----------------
__device__ __align__(16) float g_Q[N_NODES * HD];
__device__ __align__(16) float g_K[N_NODES * HD];
__device__ __align__(16) float g_V[N_NODES * HD];
__device__ __align__(16) float g_w[N_EDGES * HEADS];   // exp(clamped score)
__device__ int g_count[N_NODES];
__device__ int g_off[N_NODES + 1];
__device__ int g_cursor[N_NODES];
__device__ int g_order[N_EDGES];
__device__ int g_bsum[SCAN_BLK];
__device__ int g_boff[SCAN_BLK];
// precomputed EW hi/lo in frag layout (row stride 36 words = 144B)
__device__ __align__(16) unsigned g_Bhi[128 * 36];
__device__ __align__(16) unsigned g_Blo[128 * 36];

// ---------------- f32x2 packed FMA helpers (qkv kernel) ----------------
__device__ __forceinline__ unsigned long long pk2(float lo, float hi) {
    unsigned long long r;
    asm("mov.b64 %0, {%1, %2};" : "=l"(r) : "f"(lo), "f"(hi));
    return r;
}
__device__ __forceinline__ void fma2(unsigned long long& d, unsigned long long a, unsigned long long b) {
    asm("fma.rn.f32x2 %0, %1, %2, %0;" : "+l"(d) : "l"(a), "l"(b));
}
__device__ __forceinline__ float2 upk2(unsigned long long v) {
    float lo, hi;
    asm("mov.b64 {%0, %1}, %2;" : "=f"(lo), "=f"(hi) : "l"(v));
    return make_float2(lo, hi);
}

// bf16 split helpers
__device__ __forceinline__ uint32_t bfpack(float x, float y) {
    __nv_bfloat162 h = __floats2bfloat162_rn(x, y);
    return *reinterpret_cast<uint32_t*>(&h);
}

// mma.sync m16n8k16 bf16 (standard PTX)
__device__ __forceinline__ void mma16816(float* d,
    uint32_t a0, uint32_t a1, uint32_t a2, uint32_t a3, uint32_t b0, uint32_t b1) {
    asm volatile(
        "mma.sync.aligned.m16n8k16.row.col.f32.bf16.bf16.f32 "
        "{%0,%1,%2,%3}, {%4,%5,%6,%7}, {%8,%9}, {%0,%1,%2,%3};"
        : "+f"(d[0]), "+f"(d[1]), "+f"(d[2]), "+f"(d[3])
        : "r"(a0), "r"(a1), "r"(a2), "r"(a3), "r"(b0), "r"(b1));
}

// ---------------- kernel 1: QKV = x @ qkv_weight.T + bias ----------------
__global__ __launch_bounds__(256) void qkv_kernel(
    const float* __restrict__ x, const float* __restrict__ W, const float* __restrict__ bias)
{
    __shared__ float xS[64 * 68];
    __shared__ float wS[64 * 68];
    const int part = blockIdx.y;
    const int row0 = blockIdx.x * 64;
    const int tid = threadIdx.x;

    #pragma unroll
    for (int p = 0; p < 4; p++) {
        int idx = tid + p * 256;
        int r = idx >> 4, c4 = idx & 15;
        float4 v = make_float4(0.f, 0.f, 0.f, 0.f);
        int gr = row0 + r;
        if (gr < N_NODES) v = ((const float4*)x)[gr * 16 + c4];
        *(float4*)&xS[r * 68 + c4 * 4] = v;
    }
    #pragma unroll
    for (int p = 0; p < 4; p++) {
        int idx = tid + p * 256;
        int c = idx >> 4, f = idx & 15;
        float4 v = ((const float4*)W)[(part * 64 + c) * 16 + f];
        wS[(f * 4 + 0) * 68 + c] = v.x;
        wS[(f * 4 + 1) * 68 + c] = v.y;
        wS[(f * 4 + 2) * 68 + c] = v.z;
        wS[(f * 4 + 3) * 68 + c] = v.w;
    }
    __syncthreads();

    const int tx = tid & 15, ty = tid >> 4;
    unsigned long long acc[4][2];
    #pragma unroll
    for (int i = 0; i < 4; i++) { acc[i][0] = 0ull; acc[i][1] = 0ull; }

    #pragma unroll 4
    for (int k = 0; k < 64; k++) {
        float4 b = *(float4*)&wS[k * 68 + tx * 4];
        unsigned long long b0 = pk2(b.x, b.y), b1 = pk2(b.z, b.w);
        #pragma unroll
        for (int i = 0; i < 4; i++) {
            float a = xS[(ty * 4 + i) * 68 + k];
            unsigned long long a2 = pk2(a, a);
            fma2(acc[i][0], a2, b0);
            fma2(acc[i][1], a2, b1);
        }
    }

    float* outBase = (part == 0) ? g_Q : (part == 1 ? g_K : g_V);
    float4 bv = ((const float4*)bias)[part * 16 + tx];
    #pragma unroll
    for (int i = 0; i < 4; i++) {
        int gr = row0 + ty * 4 + i;
        if (gr < N_NODES) {
            float2 p0 = upk2(acc[i][0]), p1 = upk2(acc[i][1]);
            float4 o = make_float4(p0.x + bv.x, p0.y + bv.y, p1.x + bv.z, p1.y + bv.w);
            *(float4*)&outBase[gr * 64 + tx * 4] = o;
        }
    }
}

// ---------------- prep: convert EW -> hi/lo bf16 frag layout (once) ----------------
__global__ __launch_bounds__(256) void prep_kernel(const float* __restrict__ EW) {
    const int tid = threadIdx.x;
    const int r = tid >> 1;
    const int cb = (tid & 1) * 32;
    const float4* brow = (const float4*)(EW + (size_t)r * 64 + cb);
    uint2* bh = (uint2*)g_Bhi;
    uint2* bl = (uint2*)g_Blo;
    #pragma unroll
    for (int q = 0; q < 8; q++) {
        float4 u = brow[q];
        __nv_bfloat16 hx = __float2bfloat16(u.x), hy = __float2bfloat16(u.y);
        __nv_bfloat16 hz = __float2bfloat16(u.z), hw = __float2bfloat16(u.w);
        uint32_t h0 = bfpack(__bfloat162float(hx), __bfloat162float(hy));
        uint32_t h1 = bfpack(__bfloat162float(hz), __bfloat162float(hw));
        uint32_t l0 = bfpack(u.x - __bfloat162float(hx), u.y - __bfloat162float(hy));
        uint32_t l1 = bfpack(u.z - __bfloat162float(hz), u.w - __bfloat162float(hw));
        int p = r * 18 + cb / 4 + q;       // uint2 index
        bh[p] = make_uint2(h0, h1);
        bl[p] = make_uint2(l0, l1);
    }
}

// ---------------- CSR construction ----------------
__global__ void zero_kernel() {
    int i = blockIdx.x * blockDim.x + threadIdx.x;
    if (i < N_NODES) g_count[i] = 0;
}
__global__ __launch_bounds__(256) void scanA_kernel() {
    __shared__ int ws[8];
    int t = threadIdx.x, i = blockIdx.x * 256 + t;
    int v = (i < N_NODES) ? g_count[i] : 0;
    #pragma unroll
    for (int o = 16; o > 0; o >>= 1) v += __shfl_down_sync(0xffffffffu, v, o);
    if ((t & 31) == 0) ws[t >> 5] = v;
    __syncthreads();
    if (t == 0) {
        int s = 0;
        #pragma unroll
        for (int w = 0; w < 8; w++) s += ws[w];
        g_bsum[blockIdx.x] = s;
    }
}
__global__ __launch_bounds__(256) void scanB_kernel() {
    __shared__ int ws[8];
    int t = threadIdx.x, lane = t & 31, w = t >> 5;
    int v = (t < SCAN_BLK) ? g_bsum[t] : 0;
    int x = v;
    #pragma unroll
    for (int o = 1; o < 32; o <<= 1) {
        int y = __shfl_up_sync(0xffffffffu, x, o);
        if (lane >= o) x += y;
    }
    if (lane == 31) ws[w] = x;
    __syncthreads();
    if (t == 0) {
        int run = 0;
        #pragma unroll
        for (int k = 0; k < 8; k++) { int tmp = ws[k]; ws[k] = run; run += tmp; }
    }
    __syncthreads();
    if (t < SCAN_BLK) g_boff[t] = x - v + ws[w];
    if (t == 0) g_off[N_NODES] = N_EDGES;
}
__global__ __launch_bounds__(256) void scanC_kernel() {
    __shared__ int ws[8];
    int t = threadIdx.x, lane = t & 31, w = t >> 5;
    int i = blockIdx.x * 256 + t;
    int v = (i < N_NODES) ? g_count[i] : 0;
    int x = v;
    #pragma unroll
    for (int o = 1; o < 32; o <<= 1) {
        int y = __shfl_up_sync(0xffffffffu, x, o);
        if (lane >= o) x += y;
    }
    if (lane == 31) ws[w] = x;
    __syncthreads();
    if (t == 0) {
        int run = 0;
        #pragma unroll
        for (int k = 0; k < 8; k++) { int tmp = ws[k]; ws[k] = run; run += tmp; }
    }
    __syncthreads();
    if (i < N_NODES) {
        int excl = x - v + ws[w] + g_boff[blockIdx.x];
        g_off[i] = excl;
        g_cursor[i] = excl;
    }
}
__global__ void scatter_kernel(const int* __restrict__ eidx) {
    int e = blockIdx.x * blockDim.x + threadIdx.x;
    if (e < N_EDGES) {
        int dst = eidx[e];
        int pos = atomicAdd(&g_cursor[dst], 1);
        g_order[pos] = e;
    }
}

// ---------------- kernel 2: split-bf16 HMMA edge GEMM, 2-D warp tiling ----------
// D[128 edges, 128 cols] = cf_tile @ EW^T via mma.sync m16n8k16 bf16, 3 passes.
// 8 warps as 4m x 2n: warp (wm, wn) owns edges wm*32..+31 and cols
// {wn*32..+31} u {64+wn*32..+31}  (matching Ew/Eb pairs stay in-warp).
// Per warp-ks: 16 A-LDS + 32 B-LDS + 48 MMA (was 72 LDS).
// In-register epilogue; per-edge g_count atomicAdd fused.
#define SM_AHI 0
#define SM_ALO 18432
#define SM_BHI 36864
#define SM_BLO 55296
#define SM_MISC 73728                     // sDst 512 | sSrc 512 | awS 256 | ebS 512
#define SMEM_EDGE (SM_MISC + 512 + 512 + 256 + 512)
#define ASTRIDE 144                       // bytes per bf16 row (72 elems)

__global__ __launch_bounds__(256, 2) void edge_kernel(
    const float* __restrict__ cf,
    const float* __restrict__ Ebias, const int* __restrict__ eidx,
    const float* __restrict__ Aw, float* __restrict__ conn_out)
{
    extern __shared__ char smem[];
    const int tid = threadIdx.x;
    const int e0 = blockIdx.x * 128;

    int* sDst = (int*)(smem + SM_MISC);
    int* sSrc = (int*)(smem + SM_MISC + 512);
    float* awS = (float*)(smem + SM_MISC + 1024);
    float* ebS = (float*)(smem + SM_MISC + 1280);

    // ---- A loader: fast truncation split fp32 -> (hi, lo) bf16 pairs ----
    {
        const int r = tid >> 1;
        const int cb = (tid & 1) * 32;
        const float4* arow = (const float4*)(cf + (size_t)(e0 + r) * 64 + cb);
        #pragma unroll
        for (int q = 0; q < 8; q++) {
            float4 v = arow[q];
            uint32_t x0 = __float_as_uint(v.x), x1 = __float_as_uint(v.y);
            uint32_t x2 = __float_as_uint(v.z), x3 = __float_as_uint(v.w);
            uint32_t h0 = __byte_perm(x0, x1, 0x7632);   // (x1.hi16, x0.hi16)
            uint32_t h1 = __byte_perm(x2, x3, 0x7632);
            float hx0 = __uint_as_float(x0 & 0xFFFF0000u);
            float hx1 = __uint_as_float(x1 & 0xFFFF0000u);
            float hx2 = __uint_as_float(x2 & 0xFFFF0000u);
            float hx3 = __uint_as_float(x3 & 0xFFFF0000u);
            uint32_t l0 = bfpack(v.x - hx0, v.y - hx1);
            uint32_t l1 = bfpack(v.z - hx2, v.w - hx3);
            uint32_t off = r * ASTRIDE + (cb + q * 4) * 2;
            *(uint2*)(smem + SM_AHI + off) = make_uint2(h0, h1);
            *(uint2*)(smem + SM_ALO + off) = make_uint2(l0, l1);
        }
    }
    // ---- B loader: plain copy of preconverted frag-layout tiles ----
    {
        const uint4* bh = (const uint4*)g_Bhi;
        const uint4* bl = (const uint4*)g_Blo;
        uint4* dh = (uint4*)(smem + SM_BHI);
        uint4* dl = (uint4*)(smem + SM_BLO);
        #pragma unroll
        for (int i = tid; i < 1152; i += 256) { dh[i] = bh[i]; dl[i] = bl[i]; }
    }
    if (tid < 128) {
        int dv = eidx[e0 + tid];
        int sv = eidx[N_EDGES + e0 + tid];
        sDst[tid] = dv;
        sSrc[tid] = sv;
        atomicAdd(&g_count[dv], 1);       // fused count_kernel
    }
    if (tid >= 128 && tid < 192) awS[tid - 128] = Aw[tid - 128];
    if (tid >= 64 && tid < 192) ebS[tid - 64] = Ebias[tid - 64];
    __syncthreads();

    // ---- MMA mainloop (warp tile 32 edges x 64 cols) ----
    const int wid = tid >> 5, lane = tid & 31;
    const int gid = lane >> 2, tig = lane & 3;
    const int wm = wid >> 1;               // m-group: edges wm*32..+31
    const int wn = wid & 1;                // n-half
    const int m0 = wm * 32;
    const int wn32 = wn * 32;

    float d[2][8][4];
    #pragma unroll
    for (int mt = 0; mt < 2; mt++)
        #pragma unroll
        for (int nt = 0; nt < 8; nt++)
            #pragma unroll
            for (int p = 0; p < 4; p++) d[mt][nt][p] = 0.f;

    #pragma unroll 1
    for (int ks = 0; ks < 4; ks++) {
        const uint32_t k0b = (ks * 16 + tig * 2) * 2;
        uint32_t ah[2][4], al[2][4];
        #pragma unroll
        for (int mt = 0; mt < 2; mt++) {
            const uint32_t ro = (m0 + mt * 16 + gid) * ASTRIDE + k0b;
            ah[mt][0] = *(const uint32_t*)(smem + SM_AHI + ro);
            ah[mt][1] = *(const uint32_t*)(smem + SM_AHI + ro + 8 * ASTRIDE);
            ah[mt][2] = *(const uint32_t*)(smem + SM_AHI + ro + 16);
            ah[mt][3] = *(const uint32_t*)(smem + SM_AHI + ro + 8 * ASTRIDE + 16);
            al[mt][0] = *(const uint32_t*)(smem + SM_ALO + ro);
            al[mt][1] = *(const uint32_t*)(smem + SM_ALO + ro + 8 * ASTRIDE);
            al[mt][2] = *(const uint32_t*)(smem + SM_ALO + ro + 16);
            al[mt][3] = *(const uint32_t*)(smem + SM_ALO + ro + 8 * ASTRIDE + 16);
        }
        #pragma unroll
        for (int nt = 0; nt < 8; nt++) {
            const int cbase = wn32 + (nt & 3) * 8 + ((nt >> 2) * 64);
            const uint32_t noff = (cbase + gid) * ASTRIDE + k0b;
            uint32_t bh0 = *(const uint32_t*)(smem + SM_BHI + noff);
            uint32_t bh1 = *(const uint32_t*)(smem + SM_BHI + noff + 16);
            uint32_t bl0 = *(const uint32_t*)(smem + SM_BLO + noff);
            uint32_t bl1 = *(const uint32_t*)(smem + SM_BLO + noff + 16);
            #pragma unroll
            for (int mt = 0; mt < 2; mt++) {
                mma16816(d[mt][nt], ah[mt][0], ah[mt][1], ah[mt][2], ah[mt][3], bh0, bh1);
                mma16816(d[mt][nt], ah[mt][0], ah[mt][1], ah[mt][2], ah[mt][3], bl0, bl1);
                mma16816(d[mt][nt], al[mt][0], al[mt][1], al[mt][2], al[mt][3], bh0, bh1);
            }
        }
    }

    // ---- in-register epilogue: 4 edge rows x 4 col-octets per thread ----
    const int c0 = tig * 2;
    #pragma unroll
    for (int er = 0; er < 4; er++) {
        const int mt = er >> 1, half = er & 1;
        const int el = m0 + mt * 16 + half * 8 + gid;
        const int e = e0 + el;
        const int dn = sDst[el], sn = sSrc[el];
        float wv[4];
        #pragma unroll
        for (int nt = 0; nt < 4; nt++) {
            const int cc = wn32 + nt * 8 + c0;
            const int h = wn * 4 + nt;
            float2 q2 = *(const float2*)&g_Q[(size_t)dn * 64 + cc];
            float2 k2 = *(const float2*)&g_K[(size_t)sn * 64 + cc];
            float qk0 = q2.x + k2.x, qk1 = q2.y + k2.y;
            float ew0 = d[mt][nt][half * 2 + 0] + ebS[cc];
            float ew1 = d[mt][nt][half * 2 + 1] + ebS[cc + 1];
            float eb0 = d[mt][nt + 4][half * 2 + 0] + ebS[64 + cc];
            float eb1 = d[mt][nt + 4][half * 2 + 1] + ebS[64 + cc + 1];
            float c1a = qk0 * ew0;
            float c1b = qk1 * ew1;
            float conn0 = fmaxf(copysignf(sqrtf(fabsf(c1a)), c1a) + eb0, 0.f);
            float conn1 = fmaxf(copysignf(sqrtf(fabsf(c1b)), c1b) + eb1, 0.f);
            *(float2*)&conn_out[(long long)e * 64 + cc] = make_float2(conn0, conn1);
            float sp = conn0 * awS[c0 * 8 + h] + conn1 * awS[(c0 + 1) * 8 + h];
            sp += __shfl_xor_sync(0xffffffffu, sp, 1);
            sp += __shfl_xor_sync(0xffffffffu, sp, 2);
            wv[nt] = expf(fminf(fmaxf(sp, -CLAMP_V), CLAMP_V));
        }
        if (tig == 0)
            *(float4*)&g_w[(size_t)e * 8 + wn * 4] = make_float4(wv[0], wv[1], wv[2], wv[3]);
    }
}

// ---------------- kernel 3: per-node aggregation (warp per node) ----------------
__global__ __launch_bounds__(256) void node_kernel(
    const float* __restrict__ conn_out, const int* __restrict__ eidx,
    const float* __restrict__ Bw, float* __restrict__ No)
{
    __shared__ float bwS[512];
    int tid = threadIdx.x;
    bwS[tid] = Bw[tid];
    bwS[tid + 256] = Bw[tid + 256];
    __syncthreads();

    const int warp = tid >> 5, lane = tid & 31;
    const int n = blockIdx.x * 8 + warp;
    const int j0 = g_off[n], j1 = g_off[n + 1];
    const int h0 = lane >> 3, h1 = h0 + 4, c = lane & 7, base = lane & 24;
    const int* srcArr = eidx + N_EDGES;

    float s0 = 0.f, s1 = 0.f, agg0 = 0.f, agg1 = 0.f, rv0 = 0.f, rv1 = 0.f;
    int e = (j0 < j1) ? g_order[j0] : 0;
    for (int j = j0; j < j1; j++) {
        int e_next = (j + 1 < j1) ? g_order[j + 1] : 0;
        int src = srcArr[e];
        float w0 = g_w[e * 8 + h0];
        float w1 = g_w[e * 8 + h1];
        float c0 = conn_out[(long long)e * 64 + lane];
        float c1 = conn_out[(long long)e * 64 + 32 + lane];
        float v0 = g_V[src * 64 + lane];
        float v1 = g_V[src * 64 + 32 + lane];
        s0 += w0; s1 += w1;
        agg0 = fmaf(w0, v0, agg0); rv0 = fmaf(w0, c0, rv0);
        agg1 = fmaf(w1, v1, agg1); rv1 = fmaf(w1, c1, rv1);
        e = e_next;
    }
    float inv0 = (s0 > 0.f) ? 1.f / s0 : 0.f;
    float inv1 = (s1 > 0.f) ? 1.f / s1 : 0.f;
    float rn0 = rv0 * inv0, rn1 = rv1 * inv1;
    float o0 = 0.f, o1 = 0.f;
    #pragma unroll
    for (int dd = 0; dd < 8; dd++) {
        float r0 = __shfl_sync(0xffffffffu, rn0, base + dd);
        float r1 = __shfl_sync(0xffffffffu, rn1, base + dd);
        o0 = fmaf(r0, bwS[dd * 64 + h0 * 8 + c], o0);
        o1 = fmaf(r1, bwS[dd * 64 + h1 * 8 + c], o1);
    }
    No[n * 64 + lane] = fmaf(agg0, inv0, o0);
    No[n * 64 + 32 + lane] = fmaf(agg1, inv1, o1);
}

// ---------------- launch ----------------
extern "C" void kernel_launch(void* const* d_in, const int* in_sizes, int n_in,
                              void* d_out, int out_size)
{
    const float* x       = (const float*)d_in[0];
    const float* cf      = (const float*)d_in[1];
    const int*   eidx    = (const int*)d_in[2];
    const float* qkvW    = (const float*)d_in[3];
    const float* qkvB    = (const float*)d_in[4];
    const float* EW      = (const float*)d_in[5];
    const float* EB      = (const float*)d_in[6];
    const float* Aw      = (const float*)d_in[7];
    const float* Bw      = (const float*)d_in[8];

    float* No = (float*)d_out;
    float* conn_out = No + (size_t)N_NODES * 64;

    cudaFuncSetAttribute(edge_kernel, cudaFuncAttributeMaxDynamicSharedMemorySize, SMEM_EDGE);

    // ncu (-s 5 -c 1) profiles OUR 4th launch -> edge_kernel.
    zero_kernel<<<(N_NODES + 255) / 256, 256>>>();                         // 1
    qkv_kernel<<<dim3((N_NODES + 63) / 64, 3), 256>>>(x, qkvW, qkvB);      // 2
    prep_kernel<<<1, 256>>>(EW);                                           // 3
    edge_kernel<<<N_EDGES / 128, 256, SMEM_EDGE>>>(cf, EB, eidx, Aw, conn_out); // 4 <- profiled
    scanA_kernel<<<SCAN_BLK, 256>>>();                                     // 5
    scanB_kernel<<<1, 256>>>();                                            // 6
    scanC_kernel<<<SCAN_BLK, 256>>>();                                     // 7
    scatter_kernel<<<(N_EDGES + 255) / 256, 256>>>(eidx);                  // 8
    node_kernel<<<N_NODES / 8, 256>>>(conn_out, eidx, Bw, No);             // 9
}